// round 13
// baseline (speedup 1.0000x reference)
#include <cuda_runtime.h>
#include <cuda_fp16.h>
#include <math.h>

#define NMAX   50000
#define HEADS  4
#define HID    64
#define GRAPHS 64
#define NEG    0.2f
#define BN_EPS 1e-5f
#define EMAXT  460000

// ---------------- scratch (device globals; no allocations allowed) ----------
// g_xh / g_agg hold half2 words: word j of a row = channels (2j, 2j+1)
__device__ __align__(16) unsigned g_xh [NMAX * 128];
__device__ __align__(16) unsigned g_agg[NMAX * 128];
__device__ __align__(16) float g_as [NMAX * 4];
__device__ __align__(16) float g_ad [NMAX * 4];
__device__ float g_rep[3 * NMAX * 64];   // reps for jumping knowledge (fp32)
__device__ float g_hj [NMAX * 64];       // jump output (fp32)
__device__ int   g_deg[NMAX + 1];
__device__ int   g_off[NMAX + 1];
__device__ int   g_cur[NMAX];
__device__ int   g_csr[EMAXT];
__device__ int   g_bsum[128];

// ---------------- helpers ----------------
__device__ __forceinline__ unsigned pack_h2(float lo, float hi) {
    __half2 h = __floats2half2_rn(lo, hi);   // low 16 bits = lo
    return *reinterpret_cast<unsigned*>(&h);
}
__device__ __forceinline__ float2 unpack_h2(unsigned u) {
    return __half22float2(*reinterpret_cast<__half2*>(&u));
}
__device__ __forceinline__ void mma_f16(float c[4], const unsigned a[4], const unsigned b[2]) {
    asm volatile("mma.sync.aligned.m16n8k16.row.col.f32.f16.f16.f32 "
                 "{%0,%1,%2,%3},{%4,%5,%6,%7},{%8,%9},{%0,%1,%2,%3};"
                 : "+f"(c[0]), "+f"(c[1]), "+f"(c[2]), "+f"(c[3])
                 : "r"(a[0]), "r"(a[1]), "r"(a[2]), "r"(a[3]), "r"(b[0]), "r"(b[1]));
}
// permuted position of k-pair P (P in 0..15 within a 32-k tile)
__device__ __forceinline__ int pairpos(int P) {
    return (P & 8) + 2 * (P & 3) + ((P >> 2) & 1);
}

// ---------------- init ----------------
__global__ void init_kernel(int n) {
    int i = blockIdx.x * blockDim.x + threadIdx.x;
    if (i < n) g_deg[i] = 1;                 // self loop
}

__global__ void count_kernel(const int* __restrict__ ei, int e) {
    int i = blockIdx.x * blockDim.x + threadIdx.x;
    if (i < e) atomicAdd(&g_deg[ei[e + i]], 1);   // dst row is second
}

// ---- multi-block scan: A (local scan), B (block sums), C (apply + csr init)
__global__ void scanA_kernel(int n) {
    __shared__ int wsum[32];
    int tid = threadIdx.x, lane = tid & 31, wid = tid >> 5;
    int i = blockIdx.x * 1024 + tid;
    int v = (i < n) ? g_deg[i] : 0;
    int incl = v;
#pragma unroll
    for (int o = 1; o < 32; o <<= 1) {
        int t = __shfl_up_sync(0xffffffffu, incl, o);
        if (lane >= o) incl += t;
    }
    if (lane == 31) wsum[wid] = incl;
    __syncthreads();
    if (wid == 0) {
        int s = wsum[lane];
#pragma unroll
        for (int o = 1; o < 32; o <<= 1) {
            int t = __shfl_up_sync(0xffffffffu, s, o);
            if (lane >= o) s += t;
        }
        wsum[lane] = s;
    }
    __syncthreads();
    int wpre = wid ? wsum[wid - 1] : 0;
    if (i < n) g_off[i] = wpre + incl - v;
    if (tid == 0) g_bsum[blockIdx.x] = wsum[31];
}

__global__ void scanB_kernel(int nb, int n) {
    __shared__ int wsum[32];
    int tid = threadIdx.x, lane = tid & 31, wid = tid >> 5;
    int v = (tid < nb) ? g_bsum[tid] : 0;
    int incl = v;
#pragma unroll
    for (int o = 1; o < 32; o <<= 1) {
        int t = __shfl_up_sync(0xffffffffu, incl, o);
        if (lane >= o) incl += t;
    }
    if (lane == 31) wsum[wid] = incl;
    __syncthreads();
    if (wid == 0) {
        int s = wsum[lane];
#pragma unroll
        for (int o = 1; o < 32; o <<= 1) {
            int t = __shfl_up_sync(0xffffffffu, s, o);
            if (lane >= o) s += t;
        }
        wsum[lane] = s;
    }
    __syncthreads();
    int wpre = wid ? wsum[wid - 1] : 0;
    int excl = wpre + incl - v;
    if (tid < nb) g_bsum[tid] = excl;
    if (tid == nb - 1) g_off[n] = excl + v;
}

__global__ void scanC_kernel(int n) {
    int i = blockIdx.x * 1024 + threadIdx.x;
    if (i < n) {
        int off = g_off[i] + g_bsum[blockIdx.x];
        g_off[i] = off;
        g_csr[off] = i;            // self loop in slot 0
        g_cur[i] = off + 1;
    }
}

__global__ void fill_edges_kernel(const int* __restrict__ ei, int e) {
    int i = blockIdx.x * blockDim.x + threadIdx.x;
    if (i < e) {
        int dst = ei[e + i];
        int pos = atomicAdd(&g_cur[dst], 1);
        g_csr[pos] = ei[i];                  // src
    }
}

// ---------- fp16 tensor-core GEMM (m16n8k16, fp32 accum) ----------
// BM=128, BN=64, BK=32, 256 threads (8 warps: 4x2, warp tile 32x32)
// AMODE 0: A fp32 row-major [M,K]. AMODE 1: jump-concat fp32. AMODE 2: A half2 row-major.
// EPI 0: none.  EPI 1: +bias.  EPI 2: +bias, BN, ELU.
// ATT 1: also compute g_as/g_ad (head = blockIdx.x; requires NC=256, grid.x=4)
// OUTH 1: C is half2 words (stride NC/2), packed column pairs; EPI must be 0.
template<int AMODE, int EPI, int ATT, int OUTH>
__global__ __launch_bounds__(256, 3)
void gemm_tc(const float* __restrict__ A, const float* __restrict__ B,
             const float* __restrict__ bias,
             const float* __restrict__ gamma, const float* __restrict__ beta,
             const float* __restrict__ mean, const float* __restrict__ var,
             const float* __restrict__ a_src, const float* __restrict__ a_dst,
             void* __restrict__ Cv, int M, int K, int NC)
{
    __shared__ __align__(16) unsigned As32[128 * 24];
    __shared__ __align__(16) unsigned Bs32[64 * 24];
    __shared__ float s_attw[128];
    __shared__ float s_att[128][4];

    int tid = threadIdx.x;
    int warp = tid >> 5, lane = tid & 31;
    int wm = (warp >> 1) * 32;
    int wn = (warp & 1) * 32;
    int row0 = blockIdx.y * 128, col0 = blockIdx.x * 64;
    int g = lane >> 2, q = lane & 3;

    if (ATT && tid < 128)
        s_attw[tid] = (tid < 64) ? a_src[blockIdx.x * 64 + tid]
                                 : a_dst[blockIdx.x * 64 + tid - 64];

    float c[2][4][4] = {};

    // A staging: thread -> (row ar+32i, 4 consecutive k at ac)
    int ar = tid >> 3;
    int ac = (tid & 7) * 4;
    int aP0 = ac >> 1;
    int apos0 = pairpos(aP0);
    int apos1 = pairpos(aP0 + 1);

    // B staging: thread -> (column bn, 8 consecutive k at bkg*8)
    int bn  = tid & 63;
    int bkg = tid >> 6;
    int ebn = 2 * ((bn >> 2) & 7);
    int bpos0 = pairpos(bkg * 4 + 0) ^ ebn;
    int bpos1 = pairpos(bkg * 4 + 1) ^ ebn;
    int bpos2 = pairpos(bkg * 4 + 2) ^ ebn;
    int bpos3 = pairpos(bkg * 4 + 3) ^ ebn;
    unsigned* brow = Bs32 + bn * 24;

    for (int k0 = 0; k0 < K; k0 += 32) {
#pragma unroll
        for (int i = 0; i < 4; i++) {
            int m = ar + i * 32;
            int gm = row0 + m;
            unsigned* arow = As32 + m * 24;
            if (AMODE == 2) {
                uint2 w = make_uint2(0u, 0u);
                if (gm < M)
                    w = *(const uint2*)((const unsigned*)A + (size_t)gm * (K >> 1) + ((k0 + ac) >> 1));
                arow[apos0] = w.x;
                arow[apos1] = w.y;
            } else {
                float4 v = make_float4(0.f, 0.f, 0.f, 0.f);
                if (gm < M) {
                    if (AMODE == 0)
                        v = *(const float4*)(A + (size_t)gm * K + k0 + ac);
                    else
                        v = *(const float4*)(A + (size_t)(k0 >> 6) * (NMAX * 64)
                                               + (size_t)gm * 64 + (k0 & 63) + ac);
                }
                arow[apos0] = pack_h2(v.x, v.y);
                arow[apos1] = pack_h2(v.z, v.w);
            }
        }
        {
            const float* bg = B + (size_t)(k0 + bkg * 8) * NC + col0 + bn;
            float f0 = bg[0];
            float f1 = bg[(size_t)NC];
            float f2 = bg[(size_t)2 * NC];
            float f3 = bg[(size_t)3 * NC];
            float f4 = bg[(size_t)4 * NC];
            float f5 = bg[(size_t)5 * NC];
            float f6 = bg[(size_t)6 * NC];
            float f7 = bg[(size_t)7 * NC];
            brow[bpos0] = pack_h2(f0, f1);
            brow[bpos1] = pack_h2(f2, f3);
            brow[bpos2] = pack_h2(f4, f5);
            brow[bpos3] = pack_h2(f6, f7);
        }
        __syncthreads();
#pragma unroll
        for (int ks = 0; ks < 2; ks++) {
            unsigned a[2][4], b[4][2];
#pragma unroll
            for (int mi = 0; mi < 2; mi++) {
                const unsigned* ap = As32 + (wm + mi * 16 + g) * 24 + ks * 8 + 2 * q;
                uint2 t0 = *(const uint2*)ap;
                uint2 t1 = *(const uint2*)(ap + 8 * 24);
                a[mi][0] = t0.x;
                a[mi][1] = t1.x;
                a[mi][2] = t0.y;
                a[mi][3] = t1.y;
            }
#pragma unroll
            for (int ni = 0; ni < 4; ni++) {
                int n2 = wn + ni * 8 + g;
                const unsigned* bp = Bs32 + n2 * 24
                                   + ((ks * 8 + 2 * q) ^ (2 * ((n2 >> 2) & 7)));
                uint2 tb = *(const uint2*)bp;
                b[ni][0] = tb.x;
                b[ni][1] = tb.y;
            }
#pragma unroll
            for (int mi = 0; mi < 2; mi++)
#pragma unroll
                for (int ni = 0; ni < 4; ni++)
                    mma_f16(c[mi][ni], a[mi], b[ni]);
        }
        __syncthreads();
    }

    // epilogue
    float* Cf = (float*)Cv;
    unsigned* Ch = (unsigned*)Cv;
    float ps[2][2] = {}, pd[2][2] = {};
#pragma unroll
    for (int mi = 0; mi < 2; mi++)
#pragma unroll
        for (int ni = 0; ni < 4; ni++) {
#pragma unroll
            for (int h8 = 0; h8 < 2; h8++) {
                int r = row0 + wm + mi * 16 + h8 * 8 + g;
                float vv[2];
#pragma unroll
                for (int cc = 0; cc < 2; cc++) {
                    int cloc = wn + ni * 8 + q * 2 + cc;
                    float v = c[mi][ni][h8 * 2 + cc];
                    if (ATT) {
                        ps[mi][h8] += v * s_attw[cloc];
                        pd[mi][h8] += v * s_attw[64 + cloc];
                    }
                    if (EPI >= 1) v += bias[col0 + cloc];
                    if (EPI == 2) {
                        int cidx = col0 + cloc;
                        v = (v - mean[cidx]) * rsqrtf(var[cidx] + BN_EPS) * gamma[cidx] + beta[cidx];
                        v = v > 0.f ? v : expm1f(v);
                    }
                    vv[cc] = v;
                }
                if (r < M) {
                    int cloc0 = wn + ni * 8 + q * 2;
                    if (OUTH) {
                        Ch[(size_t)r * (NC >> 1) + ((col0 + cloc0) >> 1)] = pack_h2(vv[0], vv[1]);
                    } else {
                        Cf[(size_t)r * NC + col0 + cloc0]     = vv[0];
                        Cf[(size_t)r * NC + col0 + cloc0 + 1] = vv[1];
                    }
                }
            }
        }

    if (ATT) {
#pragma unroll
        for (int mi = 0; mi < 2; mi++)
#pragma unroll
            for (int h8 = 0; h8 < 2; h8++) {
                float vs = ps[mi][h8], vd = pd[mi][h8];
                vs += __shfl_xor_sync(0xffffffffu, vs, 1);
                vs += __shfl_xor_sync(0xffffffffu, vs, 2);
                vd += __shfl_xor_sync(0xffffffffu, vd, 1);
                vd += __shfl_xor_sync(0xffffffffu, vd, 2);
                if (q == 0) {
                    int row = wm + mi * 16 + h8 * 8 + g;
                    s_att[row][(warp & 1) * 2 + 0] = vs;
                    s_att[row][(warp & 1) * 2 + 1] = vd;
                }
            }
        __syncthreads();
        if (tid < 128) {
            int r = row0 + tid;
            if (r < M) {
                g_as[(size_t)r * 4 + blockIdx.x] = s_att[tid][0] + s_att[tid][2];
                g_ad[(size_t)r * 4 + blockIdx.x] = s_att[tid][1] + s_att[tid][3];
            }
        }
    }
}

// ---- per-edge online-softmax aggregation, shuffle-free + 2-stage prefetch ----
// Every lane broadcast-loads g_as[src] (float4, one address per warp) and
// computes the 4 head logits locally -> no __shfl on the critical path.
// Bit-identical to the shfl version (same inputs, same op order).
#define AGG_EDGE_CORE()                                                         \
    float4 ad4 = *(const float4*)(g_ad + (size_t)w * 4);                        \
    float m0 = -1e30f, m1 = -1e30f, m2 = -1e30f, m3 = -1e30f;                   \
    float s0 = 0, s1 = 0, s2 = 0, s3 = 0;                                       \
    float acc[8] = {};                                                          \
    int e0 = g_off[w], e1 = g_off[w + 1];                                       \
    int src_c = g_csr[e0];                                                      \
    float4 as_c = *(const float4*)(g_as + (size_t)src_c * 4);                   \
    const unsigned* xr_c = g_xh + (size_t)src_c * 128;                          \
    unsigned xw_c0 = xr_c[lane];                                                \
    unsigned xw_c1 = xr_c[lane + 32];                                           \
    unsigned xw_c2 = xr_c[lane + 64];                                           \
    unsigned xw_c3 = xr_c[lane + 96];                                           \
    for (int e = e0; e < e1; e++) {                                             \
        int src_n; float4 as_n;                                                 \
        unsigned xw_n0, xw_n1, xw_n2, xw_n3;                                    \
        if (e + 1 < e1) {                                                       \
            src_n = g_csr[e + 1];                                               \
            as_n = *(const float4*)(g_as + (size_t)src_n * 4);                  \
            const unsigned* xr_n = g_xh + (size_t)src_n * 128;                  \
            xw_n0 = xr_n[lane];                                                 \
            xw_n1 = xr_n[lane + 32];                                            \
            xw_n2 = xr_n[lane + 64];                                            \
            xw_n3 = xr_n[lane + 96];                                            \
        }                                                                       \
        float t;                                                                \
        t = as_c.x + ad4.x; float l0 = t > 0.f ? t : NEG * t;                   \
        t = as_c.y + ad4.y; float l1 = t > 0.f ? t : NEG * t;                   \
        t = as_c.z + ad4.z; float l2 = t > 0.f ? t : NEG * t;                   \
        t = as_c.w + ad4.w; float l3 = t > 0.f ? t : NEG * t;                   \
        float nm0 = fmaxf(m0, l0), nm1 = fmaxf(m1, l1);                         \
        float nm2 = fmaxf(m2, l2), nm3 = fmaxf(m3, l3);                         \
        float sc0 = __expf(m0 - nm0), sc1 = __expf(m1 - nm1);                   \
        float sc2 = __expf(m2 - nm2), sc3 = __expf(m3 - nm3);                   \
        float w0 = __expf(l0 - nm0), w1 = __expf(l1 - nm1);                     \
        float w2 = __expf(l2 - nm2), w3 = __expf(l3 - nm3);                     \
        s0 = s0 * sc0 + w0; s1 = s1 * sc1 + w1;                                 \
        s2 = s2 * sc2 + w2; s3 = s3 * sc3 + w3;                                 \
        m0 = nm0; m1 = nm1; m2 = nm2; m3 = nm3;                                 \
        float2 x0 = unpack_h2(xw_c0);                                           \
        float2 x1 = unpack_h2(xw_c1);                                           \
        float2 x2 = unpack_h2(xw_c2);                                           \
        float2 x3 = unpack_h2(xw_c3);                                           \
        acc[0] = acc[0] * sc0 + w0 * x0.x;                                      \
        acc[1] = acc[1] * sc0 + w0 * x0.y;                                      \
        acc[2] = acc[2] * sc1 + w1 * x1.x;                                      \
        acc[3] = acc[3] * sc1 + w1 * x1.y;                                      \
        acc[4] = acc[4] * sc2 + w2 * x2.x;                                      \
        acc[5] = acc[5] * sc2 + w2 * x2.y;                                      \
        acc[6] = acc[6] * sc3 + w3 * x3.x;                                      \
        acc[7] = acc[7] * sc3 + w3 * x3.y;                                      \
        if (e + 1 < e1) {                                                       \
            src_c = src_n; as_c = as_n;                                         \
            xw_c0 = xw_n0; xw_c1 = xw_n1; xw_c2 = xw_n2; xw_c3 = xw_n3;         \
        }                                                                       \
    }

// layer0: concat output (+bias), half2 out
__global__ void agg_concat_kernel(const float* __restrict__ bias, int n) {
    int w = blockIdx.x * (blockDim.x >> 5) + (threadIdx.x >> 5);
    int lane = threadIdx.x & 31;
    if (w >= n) return;
    AGG_EDGE_CORE();
    unsigned* o = g_agg + (size_t)w * 128;
    int cl = 2 * lane;
    o[lane]      = pack_h2(acc[0] / s0 + bias[cl],       acc[1] / s0 + bias[cl + 1]);
    o[lane + 32] = pack_h2(acc[2] / s1 + bias[64 + cl],  acc[3] / s1 + bias[64 + cl + 1]);
    o[lane + 64] = pack_h2(acc[4] / s2 + bias[128 + cl], acc[5] / s2 + bias[128 + cl + 1]);
    o[lane + 96] = pack_h2(acc[6] / s3 + bias[192 + cl], acc[7] / s3 + bias[192 + cl + 1]);
}

// layers 1/2: mean over heads + bias + BN + ELU + residual (fp32 out)
__global__ void agg_mean_kernel(const float* __restrict__ bias,
                                const float* __restrict__ gamma, const float* __restrict__ beta,
                                const float* __restrict__ mean,  const float* __restrict__ var,
                                const float* __restrict__ h_in, float* __restrict__ h_out, int n) {
    int w = blockIdx.x * (blockDim.x >> 5) + (threadIdx.x >> 5);
    int lane = threadIdx.x & 31;
    if (w >= n) return;
    AGG_EDGE_CORE();
    float i0 = 1.f / s0, i1 = 1.f / s1, i2 = 1.f / s2, i3 = 1.f / s3;
    int c0 = 2 * lane, c1 = 2 * lane + 1;
    float v0 = 0.25f * (acc[0] * i0 + acc[2] * i1 + acc[4] * i2 + acc[6] * i3) + bias[c0];
    float v1 = 0.25f * (acc[1] * i0 + acc[3] * i1 + acc[5] * i2 + acc[7] * i3) + bias[c1];
    v0 = (v0 - mean[c0]) * rsqrtf(var[c0] + BN_EPS) * gamma[c0] + beta[c0];
    v1 = (v1 - mean[c1]) * rsqrtf(var[c1] + BN_EPS) * gamma[c1] + beta[c1];
    v0 = v0 > 0.f ? v0 : expm1f(v0);
    v1 = v1 > 0.f ? v1 : expm1f(v1);
    size_t o = (size_t)w * 64;
    float2 hin = *(const float2*)(h_in + o + c0);
    float2 res = make_float2(v0 + hin.x, v1 + hin.y);
    *(float2*)(h_out + o + c0) = res;
}

// ---- fused attentional pooling + classifier: one block per graph (batch sorted)
__global__ __launch_bounds__(256)
void pool_cls_kernel(const float* __restrict__ attW, const int* __restrict__ batch,
                     const float* __restrict__ W1, const float* __restrict__ b1,
                     const float* __restrict__ W2, const float* __restrict__ b2,
                     float* __restrict__ out, int n)
{
    int gidx = blockIdx.x;
    int tid = threadIdx.x, lane = tid & 31, warp = tid >> 5;
    __shared__ float sW[64];
    __shared__ float rmax[8], rsum[8];
    __shared__ float shg[64];
    __shared__ float shid[32];
    __shared__ int sbnd[2];

    if (tid < 64) { sW[tid] = attW[tid]; shg[tid] = 0.f; }
    if (tid == 0) {
        int lo = 0, hi = n;
        while (lo < hi) { int m = (lo + hi) >> 1; if (batch[m] < gidx) lo = m + 1; else hi = m; }
        sbnd[0] = lo;
        int l2 = lo, h2 = n;
        while (l2 < h2) { int m = (l2 + h2) >> 1; if (batch[m] <= gidx) l2 = m + 1; else h2 = m; }
        sbnd[1] = l2;
    }
    __syncthreads();
    int lo = sbnd[0], hi = sbnd[1];

    float mx = -1e30f;
    for (int i = lo + warp; i < hi; i += 8) {
        const float* hr = g_hj + (size_t)i * 64;
        float p = hr[lane] * sW[lane] + hr[lane + 32] * sW[lane + 32];
#pragma unroll
        for (int o = 16; o > 0; o >>= 1) p += __shfl_xor_sync(0xffffffffu, p, o);
        mx = fmaxf(mx, p);
    }
    if (lane == 0) rmax[warp] = mx;
    __syncthreads();
    float bmax = -1e30f;
#pragma unroll
    for (int wq = 0; wq < 8; wq++) bmax = fmaxf(bmax, rmax[wq]);

    float a0 = 0.f, a1 = 0.f, se = 0.f;
    for (int i = lo + warp; i < hi; i += 8) {
        const float* hr = g_hj + (size_t)i * 64;
        float h0 = hr[lane], h1 = hr[lane + 32];
        float p = h0 * sW[lane] + h1 * sW[lane + 32];
#pragma unroll
        for (int o = 16; o > 0; o >>= 1) p += __shfl_xor_sync(0xffffffffu, p, o);
        float ev = __expf(p - bmax);
        a0 += ev * h0; a1 += ev * h1; se += ev;
    }
    if (lane == 0) rsum[warp] = se;
    atomicAdd(&shg[lane], a0);
    atomicAdd(&shg[lane + 32], a1);
    __syncthreads();

    float setot = 0.f;
#pragma unroll
    for (int wq = 0; wq < 8; wq++) setot += rsum[wq];
    float inv = (setot > 0.f) ? 1.f / setot : 0.f;

    if (tid < 32) {
        float acc = b1[tid];
        for (int cc = 0; cc < 64; cc++) acc += shg[cc] * inv * W1[cc * 32 + tid];
        shid[tid] = acc > 0.f ? acc : 0.f;
    }
    __syncthreads();
    if (tid < 2) {
        float o = b2[tid];
#pragma unroll
        for (int j = 0; j < 32; j++) o += shid[j] * W2[j * 2 + tid];
        out[gidx * 2 + tid] = o;
    }
}

// ---------------- host ----------------
extern "C" void kernel_launch(void* const* d_in, const int* in_sizes, int n_in,
                              void* d_out, int out_size) {
    const float* x        = (const float*)d_in[0];
    const int*   ei       = (const int*)d_in[1];
    const int*   batch    = (const int*)d_in[2];
    const float* conv0_W  = (const float*)d_in[3];
    const float* c0_asrc  = (const float*)d_in[4];
    const float* c0_adst  = (const float*)d_in[5];
    const float* c0_bias  = (const float*)d_in[6];
    const float* pre0_W   = (const float*)d_in[7];
    const float* pre0_b   = (const float*)d_in[8];
    const float* convs_W  = (const float*)d_in[9];
    const float* cs_asrc  = (const float*)d_in[10];
    const float* cs_adst  = (const float*)d_in[11];
    const float* cs_bias  = (const float*)d_in[12];
    const float* bn_g     = (const float*)d_in[13];
    const float* bn_b     = (const float*)d_in[14];
    const float* bn_m     = (const float*)d_in[15];
    const float* bn_v     = (const float*)d_in[16];
    const float* jump_W   = (const float*)d_in[17];
    const float* jump_b   = (const float*)d_in[18];
    const float* att_W    = (const float*)d_in[19];
    const float* cls_W1   = (const float*)d_in[21];
    const float* cls_b1   = (const float*)d_in[22];
    const float* cls_W2   = (const float*)d_in[23];
    const float* cls_b2   = (const float*)d_in[24];

    int n = in_sizes[0] / 128;
    int e = in_sizes[1] / 2;

    unsigned *p_xh, *p_agg;
    float *p_rep, *p_hj;
    cudaGetSymbolAddress((void**)&p_xh,  g_xh);
    cudaGetSymbolAddress((void**)&p_agg, g_agg);
    cudaGetSymbolAddress((void**)&p_rep, g_rep);
    cudaGetSymbolAddress((void**)&p_hj,  g_hj);

    const int T = 256;
    int nb   = (n + T - 1) / T;
    int ebN  = (e + T - 1) / T;
    int wb   = (n + 7) / 8;
    int mg   = (n + 127) / 128;
    int nb2  = (n + 1023) / 1024;

    // CSR build interleaved with layer-0 GEMM (gemm0 at launch index 3 for ncu).
    init_kernel<<<nb, T>>>(n);
    count_kernel<<<ebN, T>>>(ei, e);
    scanA_kernel<<<nb2, 1024>>>(n);
    gemm_tc<0,0,1,1><<<dim3(4, mg), 256>>>(x, conv0_W, nullptr, nullptr, nullptr,
                                           nullptr, nullptr, c0_asrc, c0_adst,
                                           p_xh, n, 128, 256);
    scanB_kernel<<<1, 1024>>>(nb2, n);
    scanC_kernel<<<nb2, 1024>>>(n);
    fill_edges_kernel<<<ebN, T>>>(ei, e);

    // ---- layer 0 aggregation (concat, half2 out) + pre0 (half A, bias+BN+ELU) ----
    agg_concat_kernel<<<wb, T>>>(c0_bias, n);
    gemm_tc<2,2,0,0><<<dim3(1, mg), 256>>>((const float*)p_agg, pre0_W, pre0_b, bn_g, bn_b,
                                           bn_m, bn_v, nullptr, nullptr,
                                           p_rep, n, 256, 64);

    // ---- layers 1,2 (mean heads, fused BN/ELU/residual in agg) ----
    for (int i = 0; i < 2; i++) {
        const float* rin  = p_rep + (size_t)i * NMAX * 64;
        float*       rout = p_rep + (size_t)(i + 1) * NMAX * 64;
        gemm_tc<0,0,1,1><<<dim3(4, mg), 256>>>(rin, convs_W + (size_t)i * 64 * 256,
                                               nullptr, nullptr, nullptr, nullptr, nullptr,
                                               cs_asrc + i * 256, cs_adst + i * 256,
                                               p_xh, n, 64, 256);
        agg_mean_kernel<<<wb, T>>>(cs_bias + i * 64,
                                   bn_g + (i + 1) * 64, bn_b + (i + 1) * 64,
                                   bn_m + (i + 1) * 64, bn_v + (i + 1) * 64,
                                   rin, rout, n);
    }

    // ---- jumping knowledge GEMM reads rep[] directly (AMODE=1), fused bias ----
    gemm_tc<1,1,0,0><<<dim3(1, mg), 256>>>(p_rep, jump_W, jump_b, nullptr, nullptr,
                                           nullptr, nullptr, nullptr, nullptr,
                                           p_hj, n, 192, 64);

    // ---- fused pooling + classifier ----
    pool_cls_kernel<<<GRAPHS, 256>>>(att_W, batch, cls_W1, cls_b1, cls_W2, cls_b2,
                                     (float*)d_out, n);
}

// round 14
// speedup vs baseline: 1.0584x; 1.0584x over previous
#include <cuda_runtime.h>
#include <cuda_fp16.h>
#include <math.h>

#define NMAX   50000
#define HEADS  4
#define HID    64
#define GRAPHS 64
#define NEG    0.2f
#define BN_EPS 1e-5f
#define EMAXT  460000

// ---------------- scratch (device globals; no allocations allowed) ----------
// g_xh / g_agg hold half2 words: word j of a row = channels (2j, 2j+1)
__device__ __align__(16) unsigned g_xh [NMAX * 128];
__device__ __align__(16) unsigned g_agg[NMAX * 128];
__device__ __align__(16) float g_as [NMAX * 4];
__device__ __align__(16) float g_ad [NMAX * 4];
__device__ float g_rep[3 * NMAX * 64];   // reps for jumping knowledge (fp32)
__device__ float g_hj [NMAX * 64];       // jump output (fp32)
__device__ int   g_deg[NMAX + 1];
__device__ int   g_off[NMAX + 1];
__device__ int   g_cur[NMAX];
__device__ int   g_csr[EMAXT];
__device__ int   g_bsum[128];

// ---------------- helpers ----------------
__device__ __forceinline__ unsigned pack_h2(float lo, float hi) {
    __half2 h = __floats2half2_rn(lo, hi);   // low 16 bits = lo
    return *reinterpret_cast<unsigned*>(&h);
}
__device__ __forceinline__ float2 unpack_h2(unsigned u) {
    return __half22float2(*reinterpret_cast<__half2*>(&u));
}
__device__ __forceinline__ void mma_f16(float c[4], const unsigned a[4], const unsigned b[2]) {
    asm volatile("mma.sync.aligned.m16n8k16.row.col.f32.f16.f16.f32 "
                 "{%0,%1,%2,%3},{%4,%5,%6,%7},{%8,%9},{%0,%1,%2,%3};"
                 : "+f"(c[0]), "+f"(c[1]), "+f"(c[2]), "+f"(c[3])
                 : "r"(a[0]), "r"(a[1]), "r"(a[2]), "r"(a[3]), "r"(b[0]), "r"(b[1]));
}
// permuted position of k-pair P (P in 0..15 within a 32-k tile)
__device__ __forceinline__ int pairpos(int P) {
    return (P & 8) + 2 * (P & 3) + ((P >> 2) & 1);
}

// ---------------- init ----------------
__global__ void init_kernel(int n) {
    int i = blockIdx.x * blockDim.x + threadIdx.x;
    if (i < n) g_deg[i] = 1;                 // self loop
}

__global__ void count_kernel(const int* __restrict__ ei, int e) {
    int i = blockIdx.x * blockDim.x + threadIdx.x;
    if (i < e) atomicAdd(&g_deg[ei[e + i]], 1);   // dst row is second
}

// ---- multi-block scan: A (local scan), B (block sums), C (apply + csr init)
__global__ void scanA_kernel(int n) {
    __shared__ int wsum[32];
    int tid = threadIdx.x, lane = tid & 31, wid = tid >> 5;
    int i = blockIdx.x * 1024 + tid;
    int v = (i < n) ? g_deg[i] : 0;
    int incl = v;
#pragma unroll
    for (int o = 1; o < 32; o <<= 1) {
        int t = __shfl_up_sync(0xffffffffu, incl, o);
        if (lane >= o) incl += t;
    }
    if (lane == 31) wsum[wid] = incl;
    __syncthreads();
    if (wid == 0) {
        int s = wsum[lane];
#pragma unroll
        for (int o = 1; o < 32; o <<= 1) {
            int t = __shfl_up_sync(0xffffffffu, s, o);
            if (lane >= o) s += t;
        }
        wsum[lane] = s;
    }
    __syncthreads();
    int wpre = wid ? wsum[wid - 1] : 0;
    if (i < n) g_off[i] = wpre + incl - v;
    if (tid == 0) g_bsum[blockIdx.x] = wsum[31];
}

__global__ void scanB_kernel(int nb, int n) {
    __shared__ int wsum[32];
    int tid = threadIdx.x, lane = tid & 31, wid = tid >> 5;
    int v = (tid < nb) ? g_bsum[tid] : 0;
    int incl = v;
#pragma unroll
    for (int o = 1; o < 32; o <<= 1) {
        int t = __shfl_up_sync(0xffffffffu, incl, o);
        if (lane >= o) incl += t;
    }
    if (lane == 31) wsum[wid] = incl;
    __syncthreads();
    if (wid == 0) {
        int s = wsum[lane];
#pragma unroll
        for (int o = 1; o < 32; o <<= 1) {
            int t = __shfl_up_sync(0xffffffffu, s, o);
            if (lane >= o) s += t;
        }
        wsum[lane] = s;
    }
    __syncthreads();
    int wpre = wid ? wsum[wid - 1] : 0;
    int excl = wpre + incl - v;
    if (tid < nb) g_bsum[tid] = excl;
    if (tid == nb - 1) g_off[n] = excl + v;
}

__global__ void scanC_kernel(int n) {
    int i = blockIdx.x * 1024 + threadIdx.x;
    if (i < n) {
        int off = g_off[i] + g_bsum[blockIdx.x];
        g_off[i] = off;
        g_csr[off] = i;            // self loop in slot 0
        g_cur[i] = off + 1;
    }
}

__global__ void fill_edges_kernel(const int* __restrict__ ei, int e) {
    int i = blockIdx.x * blockDim.x + threadIdx.x;
    if (i < e) {
        int dst = ei[e + i];
        int pos = atomicAdd(&g_cur[dst], 1);
        g_csr[pos] = ei[i];                  // src
    }
}

// ---------- fp16 tensor-core GEMM (m16n8k16, fp32 accum) ----------
// BM=128, BN=64, BK=32, 256 threads (8 warps: 4x2, warp tile 32x32)
// AMODE 0: A fp32 row-major [M,K]. AMODE 1: jump-concat fp32. AMODE 2: A half2 row-major.
// EPI 0: none.  EPI 1: +bias.  EPI 2: +bias, BN, ELU.
// ATT 1: also compute g_as/g_ad (head = blockIdx.x; requires NC=256, grid.x=4)
// OUTH 1: C is half2 words (stride NC/2), packed column pairs; EPI must be 0.
template<int AMODE, int EPI, int ATT, int OUTH>
__global__ __launch_bounds__(256, 3)
void gemm_tc(const float* __restrict__ A, const float* __restrict__ B,
             const float* __restrict__ bias,
             const float* __restrict__ gamma, const float* __restrict__ beta,
             const float* __restrict__ mean, const float* __restrict__ var,
             const float* __restrict__ a_src, const float* __restrict__ a_dst,
             void* __restrict__ Cv, int M, int K, int NC)
{
    __shared__ __align__(16) unsigned As32[128 * 24];
    __shared__ __align__(16) unsigned Bs32[64 * 24];
    __shared__ float s_attw[128];
    __shared__ float s_att[128][4];

    int tid = threadIdx.x;
    int warp = tid >> 5, lane = tid & 31;
    int wm = (warp >> 1) * 32;
    int wn = (warp & 1) * 32;
    int row0 = blockIdx.y * 128, col0 = blockIdx.x * 64;
    int g = lane >> 2, q = lane & 3;

    if (ATT && tid < 128)
        s_attw[tid] = (tid < 64) ? a_src[blockIdx.x * 64 + tid]
                                 : a_dst[blockIdx.x * 64 + tid - 64];

    float c[2][4][4] = {};

    // A staging: thread -> (row ar+32i, 4 consecutive k at ac)
    int ar = tid >> 3;
    int ac = (tid & 7) * 4;
    int aP0 = ac >> 1;
    int apos0 = pairpos(aP0);
    int apos1 = pairpos(aP0 + 1);

    // B staging: thread -> (column bn, 8 consecutive k at bkg*8)
    int bn  = tid & 63;
    int bkg = tid >> 6;
    int ebn = 2 * ((bn >> 2) & 7);
    int bpos0 = pairpos(bkg * 4 + 0) ^ ebn;
    int bpos1 = pairpos(bkg * 4 + 1) ^ ebn;
    int bpos2 = pairpos(bkg * 4 + 2) ^ ebn;
    int bpos3 = pairpos(bkg * 4 + 3) ^ ebn;
    unsigned* brow = Bs32 + bn * 24;

    for (int k0 = 0; k0 < K; k0 += 32) {
#pragma unroll
        for (int i = 0; i < 4; i++) {
            int m = ar + i * 32;
            int gm = row0 + m;
            unsigned* arow = As32 + m * 24;
            if (AMODE == 2) {
                uint2 w = make_uint2(0u, 0u);
                if (gm < M)
                    w = *(const uint2*)((const unsigned*)A + (size_t)gm * (K >> 1) + ((k0 + ac) >> 1));
                arow[apos0] = w.x;
                arow[apos1] = w.y;
            } else {
                float4 v = make_float4(0.f, 0.f, 0.f, 0.f);
                if (gm < M) {
                    if (AMODE == 0)
                        v = *(const float4*)(A + (size_t)gm * K + k0 + ac);
                    else
                        v = *(const float4*)(A + (size_t)(k0 >> 6) * (NMAX * 64)
                                               + (size_t)gm * 64 + (k0 & 63) + ac);
                }
                arow[apos0] = pack_h2(v.x, v.y);
                arow[apos1] = pack_h2(v.z, v.w);
            }
        }
        {
            const float* bg = B + (size_t)(k0 + bkg * 8) * NC + col0 + bn;
            float f0 = bg[0];
            float f1 = bg[(size_t)NC];
            float f2 = bg[(size_t)2 * NC];
            float f3 = bg[(size_t)3 * NC];
            float f4 = bg[(size_t)4 * NC];
            float f5 = bg[(size_t)5 * NC];
            float f6 = bg[(size_t)6 * NC];
            float f7 = bg[(size_t)7 * NC];
            brow[bpos0] = pack_h2(f0, f1);
            brow[bpos1] = pack_h2(f2, f3);
            brow[bpos2] = pack_h2(f4, f5);
            brow[bpos3] = pack_h2(f6, f7);
        }
        __syncthreads();
#pragma unroll
        for (int ks = 0; ks < 2; ks++) {
            unsigned a[2][4], b[4][2];
#pragma unroll
            for (int mi = 0; mi < 2; mi++) {
                const unsigned* ap = As32 + (wm + mi * 16 + g) * 24 + ks * 8 + 2 * q;
                uint2 t0 = *(const uint2*)ap;
                uint2 t1 = *(const uint2*)(ap + 8 * 24);
                a[mi][0] = t0.x;
                a[mi][1] = t1.x;
                a[mi][2] = t0.y;
                a[mi][3] = t1.y;
            }
#pragma unroll
            for (int ni = 0; ni < 4; ni++) {
                int n2 = wn + ni * 8 + g;
                const unsigned* bp = Bs32 + n2 * 24
                                   + ((ks * 8 + 2 * q) ^ (2 * ((n2 >> 2) & 7)));
                uint2 tb = *(const uint2*)bp;
                b[ni][0] = tb.x;
                b[ni][1] = tb.y;
            }
#pragma unroll
            for (int mi = 0; mi < 2; mi++)
#pragma unroll
                for (int ni = 0; ni < 4; ni++)
                    mma_f16(c[mi][ni], a[mi], b[ni]);
        }
        __syncthreads();
    }

    // epilogue
    float* Cf = (float*)Cv;
    unsigned* Ch = (unsigned*)Cv;
    float ps[2][2] = {}, pd[2][2] = {};
#pragma unroll
    for (int mi = 0; mi < 2; mi++)
#pragma unroll
        for (int ni = 0; ni < 4; ni++) {
#pragma unroll
            for (int h8 = 0; h8 < 2; h8++) {
                int r = row0 + wm + mi * 16 + h8 * 8 + g;
                float vv[2];
#pragma unroll
                for (int cc = 0; cc < 2; cc++) {
                    int cloc = wn + ni * 8 + q * 2 + cc;
                    float v = c[mi][ni][h8 * 2 + cc];
                    if (ATT) {
                        ps[mi][h8] += v * s_attw[cloc];
                        pd[mi][h8] += v * s_attw[64 + cloc];
                    }
                    if (EPI >= 1) v += bias[col0 + cloc];
                    if (EPI == 2) {
                        int cidx = col0 + cloc;
                        v = (v - mean[cidx]) * rsqrtf(var[cidx] + BN_EPS) * gamma[cidx] + beta[cidx];
                        v = v > 0.f ? v : expm1f(v);
                    }
                    vv[cc] = v;
                }
                if (r < M) {
                    int cloc0 = wn + ni * 8 + q * 2;
                    if (OUTH) {
                        Ch[(size_t)r * (NC >> 1) + ((col0 + cloc0) >> 1)] = pack_h2(vv[0], vv[1]);
                    } else {
                        Cf[(size_t)r * NC + col0 + cloc0]     = vv[0];
                        Cf[(size_t)r * NC + col0 + cloc0 + 1] = vv[1];
                    }
                }
            }
        }

    if (ATT) {
#pragma unroll
        for (int mi = 0; mi < 2; mi++)
#pragma unroll
            for (int h8 = 0; h8 < 2; h8++) {
                float vs = ps[mi][h8], vd = pd[mi][h8];
                vs += __shfl_xor_sync(0xffffffffu, vs, 1);
                vs += __shfl_xor_sync(0xffffffffu, vs, 2);
                vd += __shfl_xor_sync(0xffffffffu, vd, 1);
                vd += __shfl_xor_sync(0xffffffffu, vd, 2);
                if (q == 0) {
                    int row = wm + mi * 16 + h8 * 8 + g;
                    s_att[row][(warp & 1) * 2 + 0] = vs;
                    s_att[row][(warp & 1) * 2 + 1] = vd;
                }
            }
        __syncthreads();
        if (tid < 128) {
            int r = row0 + tid;
            if (r < M) {
                g_as[(size_t)r * 4 + blockIdx.x] = s_att[tid][0] + s_att[tid][2];
                g_ad[(size_t)r * 4 + blockIdx.x] = s_att[tid][1] + s_att[tid][3];
            }
        }
    }
}

// ---- pairwise online-softmax aggregation (2 edges/iter) + prefetch ----
// lanes 0-3 carry edge A's per-head src logits, lanes 4-7 edge B's.
// One rescale chain per PAIR. Odd trailing edge: lb forced to -1e30 ->
// exp underflows to exactly 0, contribution vanishes (branch-free mask).
#define AGG_EDGE_CORE()                                                         \
    float m0 = -1e30f, m1 = -1e30f, m2 = -1e30f, m3 = -1e30f;                   \
    float s0 = 0, s1 = 0, s2 = 0, s3 = 0;                                       \
    float acc[8] = {};                                                          \
    float adh = (lane < 8) ? g_ad[(size_t)w * 4 + (lane & 3)] : 0.f;            \
    int e0 = g_off[w], e1 = g_off[w + 1];                                       \
    int sA_c = g_csr[e0];                                                       \
    int sB_c = (e0 + 1 < e1) ? g_csr[e0 + 1] : sA_c;                            \
    float lr_c = 0.f;                                                           \
    if (lane < 4)      lr_c = g_as[(size_t)sA_c * 4 + lane];                    \
    else if (lane < 8) lr_c = g_as[(size_t)sB_c * 4 + (lane - 4)];              \
    const unsigned* xrA = g_xh + (size_t)sA_c * 128;                            \
    const unsigned* xrB = g_xh + (size_t)sB_c * 128;                            \
    unsigned xa0 = xrA[lane], xa1 = xrA[lane + 32];                             \
    unsigned xa2 = xrA[lane + 64], xa3 = xrA[lane + 96];                        \
    unsigned xb0 = xrB[lane], xb1 = xrB[lane + 32];                             \
    unsigned xb2 = xrB[lane + 64], xb3 = xrB[lane + 96];                        \
    for (int e = e0; e < e1; e += 2) {                                          \
        int sA_n, sB_n; float lr_n;                                             \
        unsigned na0, na1, na2, na3, nb0, nb1, nb2, nb3;                        \
        if (e + 2 < e1) {                                                       \
            sA_n = g_csr[e + 2];                                                \
            sB_n = (e + 3 < e1) ? g_csr[e + 3] : sA_n;                          \
            lr_n = 0.f;                                                         \
            if (lane < 4)      lr_n = g_as[(size_t)sA_n * 4 + lane];            \
            else if (lane < 8) lr_n = g_as[(size_t)sB_n * 4 + (lane - 4)];      \
            const unsigned* nxA = g_xh + (size_t)sA_n * 128;                    \
            const unsigned* nxB = g_xh + (size_t)sB_n * 128;                    \
            na0 = nxA[lane]; na1 = nxA[lane + 32];                              \
            na2 = nxA[lane + 64]; na3 = nxA[lane + 96];                         \
            nb0 = nxB[lane]; nb1 = nxB[lane + 32];                              \
            nb2 = nxB[lane + 64]; nb3 = nxB[lane + 96];                         \
        }                                                                       \
        float l = 0.f;                                                          \
        if (lane < 8) {                                                         \
            float t = lr_c + adh;                                               \
            l = t > 0.f ? t : NEG * t;                                          \
        }                                                                       \
        float la0 = __shfl_sync(0xffffffffu, l, 0);                             \
        float la1 = __shfl_sync(0xffffffffu, l, 1);                             \
        float la2 = __shfl_sync(0xffffffffu, l, 2);                             \
        float la3 = __shfl_sync(0xffffffffu, l, 3);                             \
        float lb0 = __shfl_sync(0xffffffffu, l, 4);                             \
        float lb1 = __shfl_sync(0xffffffffu, l, 5);                             \
        float lb2 = __shfl_sync(0xffffffffu, l, 6);                             \
        float lb3 = __shfl_sync(0xffffffffu, l, 7);                             \
        if (e + 1 >= e1) { lb0 = lb1 = lb2 = lb3 = -1e30f; }                    \
        float nm0 = fmaxf(m0, fmaxf(la0, lb0));                                 \
        float nm1 = fmaxf(m1, fmaxf(la1, lb1));                                 \
        float nm2 = fmaxf(m2, fmaxf(la2, lb2));                                 \
        float nm3 = fmaxf(m3, fmaxf(la3, lb3));                                 \
        float sc0 = __expf(m0 - nm0), sc1 = __expf(m1 - nm1);                   \
        float sc2 = __expf(m2 - nm2), sc3 = __expf(m3 - nm3);                   \
        float wa0 = __expf(la0 - nm0), wa1 = __expf(la1 - nm1);                 \
        float wa2 = __expf(la2 - nm2), wa3 = __expf(la3 - nm3);                 \
        float wb0 = __expf(lb0 - nm0), wb1 = __expf(lb1 - nm1);                 \
        float wb2 = __expf(lb2 - nm2), wb3 = __expf(lb3 - nm3);                 \
        s0 = s0 * sc0 + wa0 + wb0; s1 = s1 * sc1 + wa1 + wb1;                   \
        s2 = s2 * sc2 + wa2 + wb2; s3 = s3 * sc3 + wa3 + wb3;                   \
        m0 = nm0; m1 = nm1; m2 = nm2; m3 = nm3;                                 \
        float2 A0 = unpack_h2(xa0), A1 = unpack_h2(xa1);                        \
        float2 A2 = unpack_h2(xa2), A3 = unpack_h2(xa3);                        \
        float2 B0 = unpack_h2(xb0), B1 = unpack_h2(xb1);                        \
        float2 B2 = unpack_h2(xb2), B3 = unpack_h2(xb3);                        \
        acc[0] = acc[0] * sc0 + wa0 * A0.x + wb0 * B0.x;                        \
        acc[1] = acc[1] * sc0 + wa0 * A0.y + wb0 * B0.y;                        \
        acc[2] = acc[2] * sc1 + wa1 * A1.x + wb1 * B1.x;                        \
        acc[3] = acc[3] * sc1 + wa1 * A1.y + wb1 * B1.y;                        \
        acc[4] = acc[4] * sc2 + wa2 * A2.x + wb2 * B2.x;                        \
        acc[5] = acc[5] * sc2 + wa2 * A2.y + wb2 * B2.y;                        \
        acc[6] = acc[6] * sc3 + wa3 * A3.x + wb3 * B3.x;                        \
        acc[7] = acc[7] * sc3 + wa3 * A3.y + wb3 * B3.y;                        \
        if (e + 2 < e1) {                                                       \
            lr_c = lr_n;                                                        \
            xa0 = na0; xa1 = na1; xa2 = na2; xa3 = na3;                         \
            xb0 = nb0; xb1 = nb1; xb2 = nb2; xb3 = nb3;                         \
        }                                                                       \
    }

// layer0: concat output (+bias), half2 out
__global__ void agg_concat_kernel(const float* __restrict__ bias, int n) {
    int w = blockIdx.x * (blockDim.x >> 5) + (threadIdx.x >> 5);
    int lane = threadIdx.x & 31;
    if (w >= n) return;
    AGG_EDGE_CORE();
    unsigned* o = g_agg + (size_t)w * 128;
    int cl = 2 * lane;
    o[lane]      = pack_h2(acc[0] / s0 + bias[cl],       acc[1] / s0 + bias[cl + 1]);
    o[lane + 32] = pack_h2(acc[2] / s1 + bias[64 + cl],  acc[3] / s1 + bias[64 + cl + 1]);
    o[lane + 64] = pack_h2(acc[4] / s2 + bias[128 + cl], acc[5] / s2 + bias[128 + cl + 1]);
    o[lane + 96] = pack_h2(acc[6] / s3 + bias[192 + cl], acc[7] / s3 + bias[192 + cl + 1]);
}

// layers 1/2: mean over heads + bias + BN + ELU + residual (fp32 out)
__global__ void agg_mean_kernel(const float* __restrict__ bias,
                                const float* __restrict__ gamma, const float* __restrict__ beta,
                                const float* __restrict__ mean,  const float* __restrict__ var,
                                const float* __restrict__ h_in, float* __restrict__ h_out, int n) {
    int w = blockIdx.x * (blockDim.x >> 5) + (threadIdx.x >> 5);
    int lane = threadIdx.x & 31;
    if (w >= n) return;
    AGG_EDGE_CORE();
    float i0 = 1.f / s0, i1 = 1.f / s1, i2 = 1.f / s2, i3 = 1.f / s3;
    int c0 = 2 * lane, c1 = 2 * lane + 1;
    float v0 = 0.25f * (acc[0] * i0 + acc[2] * i1 + acc[4] * i2 + acc[6] * i3) + bias[c0];
    float v1 = 0.25f * (acc[1] * i0 + acc[3] * i1 + acc[5] * i2 + acc[7] * i3) + bias[c1];
    v0 = (v0 - mean[c0]) * rsqrtf(var[c0] + BN_EPS) * gamma[c0] + beta[c0];
    v1 = (v1 - mean[c1]) * rsqrtf(var[c1] + BN_EPS) * gamma[c1] + beta[c1];
    v0 = v0 > 0.f ? v0 : expm1f(v0);
    v1 = v1 > 0.f ? v1 : expm1f(v1);
    size_t o = (size_t)w * 64;
    float2 hin = *(const float2*)(h_in + o + c0);
    float2 res = make_float2(v0 + hin.x, v1 + hin.y);
    *(float2*)(h_out + o + c0) = res;
}

// ---- fused attentional pooling + classifier: one block per graph (batch sorted)
__global__ __launch_bounds__(256)
void pool_cls_kernel(const float* __restrict__ attW, const int* __restrict__ batch,
                     const float* __restrict__ W1, const float* __restrict__ b1,
                     const float* __restrict__ W2, const float* __restrict__ b2,
                     float* __restrict__ out, int n)
{
    int gidx = blockIdx.x;
    int tid = threadIdx.x, lane = tid & 31, warp = tid >> 5;
    __shared__ float sW[64];
    __shared__ float rmax[8], rsum[8];
    __shared__ float shg[64];
    __shared__ float shid[32];
    __shared__ int sbnd[2];

    if (tid < 64) { sW[tid] = attW[tid]; shg[tid] = 0.f; }
    if (tid == 0) {
        int lo = 0, hi = n;
        while (lo < hi) { int m = (lo + hi) >> 1; if (batch[m] < gidx) lo = m + 1; else hi = m; }
        sbnd[0] = lo;
        int l2 = lo, h2 = n;
        while (l2 < h2) { int m = (l2 + h2) >> 1; if (batch[m] <= gidx) l2 = m + 1; else h2 = m; }
        sbnd[1] = l2;
    }
    __syncthreads();
    int lo = sbnd[0], hi = sbnd[1];

    float mx = -1e30f;
    for (int i = lo + warp; i < hi; i += 8) {
        const float* hr = g_hj + (size_t)i * 64;
        float p = hr[lane] * sW[lane] + hr[lane + 32] * sW[lane + 32];
#pragma unroll
        for (int o = 16; o > 0; o >>= 1) p += __shfl_xor_sync(0xffffffffu, p, o);
        mx = fmaxf(mx, p);
    }
    if (lane == 0) rmax[warp] = mx;
    __syncthreads();
    float bmax = -1e30f;
#pragma unroll
    for (int wq = 0; wq < 8; wq++) bmax = fmaxf(bmax, rmax[wq]);

    float a0 = 0.f, a1 = 0.f, se = 0.f;
    for (int i = lo + warp; i < hi; i += 8) {
        const float* hr = g_hj + (size_t)i * 64;
        float h0 = hr[lane], h1 = hr[lane + 32];
        float p = h0 * sW[lane] + h1 * sW[lane + 32];
#pragma unroll
        for (int o = 16; o > 0; o >>= 1) p += __shfl_xor_sync(0xffffffffu, p, o);
        float ev = __expf(p - bmax);
        a0 += ev * h0; a1 += ev * h1; se += ev;
    }
    if (lane == 0) rsum[warp] = se;
    atomicAdd(&shg[lane], a0);
    atomicAdd(&shg[lane + 32], a1);
    __syncthreads();

    float setot = 0.f;
#pragma unroll
    for (int wq = 0; wq < 8; wq++) setot += rsum[wq];
    float inv = (setot > 0.f) ? 1.f / setot : 0.f;

    if (tid < 32) {
        float acc = b1[tid];
        for (int cc = 0; cc < 64; cc++) acc += shg[cc] * inv * W1[cc * 32 + tid];
        shid[tid] = acc > 0.f ? acc : 0.f;
    }
    __syncthreads();
    if (tid < 2) {
        float o = b2[tid];
#pragma unroll
        for (int j = 0; j < 32; j++) o += shid[j] * W2[j * 2 + tid];
        out[gidx * 2 + tid] = o;
    }
}

// ---------------- host ----------------
extern "C" void kernel_launch(void* const* d_in, const int* in_sizes, int n_in,
                              void* d_out, int out_size) {
    const float* x        = (const float*)d_in[0];
    const int*   ei       = (const int*)d_in[1];
    const int*   batch    = (const int*)d_in[2];
    const float* conv0_W  = (const float*)d_in[3];
    const float* c0_asrc  = (const float*)d_in[4];
    const float* c0_adst  = (const float*)d_in[5];
    const float* c0_bias  = (const float*)d_in[6];
    const float* pre0_W   = (const float*)d_in[7];
    const float* pre0_b   = (const float*)d_in[8];
    const float* convs_W  = (const float*)d_in[9];
    const float* cs_asrc  = (const float*)d_in[10];
    const float* cs_adst  = (const float*)d_in[11];
    const float* cs_bias  = (const float*)d_in[12];
    const float* bn_g     = (const float*)d_in[13];
    const float* bn_b     = (const float*)d_in[14];
    const float* bn_m     = (const float*)d_in[15];
    const float* bn_v     = (const float*)d_in[16];
    const float* jump_W   = (const float*)d_in[17];
    const float* jump_b   = (const float*)d_in[18];
    const float* att_W    = (const float*)d_in[19];
    const float* cls_W1   = (const float*)d_in[21];
    const float* cls_b1   = (const float*)d_in[22];
    const float* cls_W2   = (const float*)d_in[23];
    const float* cls_b2   = (const float*)d_in[24];

    int n = in_sizes[0] / 128;
    int e = in_sizes[1] / 2;

    unsigned *p_xh, *p_agg;
    float *p_rep, *p_hj;
    cudaGetSymbolAddress((void**)&p_xh,  g_xh);
    cudaGetSymbolAddress((void**)&p_agg, g_agg);
    cudaGetSymbolAddress((void**)&p_rep, g_rep);
    cudaGetSymbolAddress((void**)&p_hj,  g_hj);

    const int T = 256;
    int nb   = (n + T - 1) / T;
    int ebN  = (e + T - 1) / T;
    int wb   = (n + 7) / 8;
    int mg   = (n + 127) / 128;
    int nb2  = (n + 1023) / 1024;

    // CSR build interleaved with layer-0 GEMM (gemm0 at launch index 3 for ncu).
    init_kernel<<<nb, T>>>(n);
    count_kernel<<<ebN, T>>>(ei, e);
    scanA_kernel<<<nb2, 1024>>>(n);
    gemm_tc<0,0,1,1><<<dim3(4, mg), 256>>>(x, conv0_W, nullptr, nullptr, nullptr,
                                           nullptr, nullptr, c0_asrc, c0_adst,
                                           p_xh, n, 128, 256);
    scanB_kernel<<<1, 1024>>>(nb2, n);
    scanC_kernel<<<nb2, 1024>>>(n);
    fill_edges_kernel<<<ebN, T>>>(ei, e);

    // ---- layer 0 aggregation (concat, half2 out) + pre0 (half A, bias+BN+ELU) ----
    agg_concat_kernel<<<wb, T>>>(c0_bias, n);
    gemm_tc<2,2,0,0><<<dim3(1, mg), 256>>>((const float*)p_agg, pre0_W, pre0_b, bn_g, bn_b,
                                           bn_m, bn_v, nullptr, nullptr,
                                           p_rep, n, 256, 64);

    // ---- layers 1,2 (mean heads, fused BN/ELU/residual in agg) ----
    for (int i = 0; i < 2; i++) {
        const float* rin  = p_rep + (size_t)i * NMAX * 64;
        float*       rout = p_rep + (size_t)(i + 1) * NMAX * 64;
        gemm_tc<0,0,1,1><<<dim3(4, mg), 256>>>(rin, convs_W + (size_t)i * 64 * 256,
                                               nullptr, nullptr, nullptr, nullptr, nullptr,
                                               cs_asrc + i * 256, cs_adst + i * 256,
                                               p_xh, n, 64, 256);
        agg_mean_kernel<<<wb, T>>>(cs_bias + i * 64,
                                   bn_g + (i + 1) * 64, bn_b + (i + 1) * 64,
                                   bn_m + (i + 1) * 64, bn_v + (i + 1) * 64,
                                   rin, rout, n);
    }

    // ---- jumping knowledge GEMM reads rep[] directly (AMODE=1), fused bias ----
    gemm_tc<1,1,0,0><<<dim3(1, mg), 256>>>(p_rep, jump_W, jump_b, nullptr, nullptr,
                                           nullptr, nullptr, nullptr, nullptr,
                                           p_hj, n, 192, 64);

    // ---- fused pooling + classifier ----
    pool_cls_kernel<<<GRAPHS, 256>>>(att_W, batch, cls_W1, cls_b1, cls_W2, cls_b2,
                                     (float*)d_out, n);
}

// round 15
// speedup vs baseline: 1.0823x; 1.0226x over previous
#include <cuda_runtime.h>
#include <cuda_fp16.h>
#include <math.h>

#define NMAX   50000
#define HEADS  4
#define HID    64
#define GRAPHS 64
#define NEG    0.2f
#define BN_EPS 1e-5f
#define EMAXT  460000

// ---------------- scratch (device globals; no allocations allowed) ----------
// g_xh / g_agg hold half2 words: word j of a row = channels (2j, 2j+1)
__device__ __align__(16) unsigned g_xh [NMAX * 128];
__device__ __align__(16) unsigned g_agg[NMAX * 128];
__device__ __align__(16) float g_as [NMAX * 4];
__device__ __align__(16) float g_ad [NMAX * 4];
__device__ float g_rep[3 * NMAX * 64];   // reps for jumping knowledge (fp32)
__device__ float g_hj [NMAX * 64];       // jump output (fp32)
__device__ int   g_deg[NMAX + 1];
__device__ int   g_off[NMAX + 1];
__device__ int   g_cur[NMAX];
__device__ int   g_csr[EMAXT];
__device__ int   g_bsum[128];

// ---------------- helpers ----------------
__device__ __forceinline__ unsigned pack_h2(float lo, float hi) {
    __half2 h = __floats2half2_rn(lo, hi);   // low 16 bits = lo
    return *reinterpret_cast<unsigned*>(&h);
}
__device__ __forceinline__ float2 unpack_h2(unsigned u) {
    return __half22float2(*reinterpret_cast<__half2*>(&u));
}
__device__ __forceinline__ void mma_f16(float c[4], const unsigned a[4], const unsigned b[2]) {
    asm volatile("mma.sync.aligned.m16n8k16.row.col.f32.f16.f16.f32 "
                 "{%0,%1,%2,%3},{%4,%5,%6,%7},{%8,%9},{%0,%1,%2,%3};"
                 : "+f"(c[0]), "+f"(c[1]), "+f"(c[2]), "+f"(c[3])
                 : "r"(a[0]), "r"(a[1]), "r"(a[2]), "r"(a[3]), "r"(b[0]), "r"(b[1]));
}
// permuted position of k-pair P (P in 0..15 within a 32-k tile)
__device__ __forceinline__ int pairpos(int P) {
    return (P & 8) + 2 * (P & 3) + ((P >> 2) & 1);
}

// ---------------- CSR build ----------------
__global__ void count_kernel(const int* __restrict__ ei, int e) {
    int i = blockIdx.x * blockDim.x + threadIdx.x;
    if (i < e) atomicAdd(&g_deg[ei[e + i]], 1);   // dst row is second
}

// ---- multi-block scan: A (local scan, +1 self loop), B (block sums), C (apply)
__global__ void scanA_kernel(int n) {
    __shared__ int wsum[32];
    int tid = threadIdx.x, lane = tid & 31, wid = tid >> 5;
    int i = blockIdx.x * 1024 + tid;
    int v = (i < n) ? g_deg[i] + 1 : 0;       // +1 = self loop
    int incl = v;
#pragma unroll
    for (int o = 1; o < 32; o <<= 1) {
        int t = __shfl_up_sync(0xffffffffu, incl, o);
        if (lane >= o) incl += t;
    }
    if (lane == 31) wsum[wid] = incl;
    __syncthreads();
    if (wid == 0) {
        int s = wsum[lane];
#pragma unroll
        for (int o = 1; o < 32; o <<= 1) {
            int t = __shfl_up_sync(0xffffffffu, s, o);
            if (lane >= o) s += t;
        }
        wsum[lane] = s;
    }
    __syncthreads();
    int wpre = wid ? wsum[wid - 1] : 0;
    if (i < n) g_off[i] = wpre + incl - v;
    if (tid == 0) g_bsum[blockIdx.x] = wsum[31];
}

__global__ void scanB_kernel(int nb, int n) {
    __shared__ int wsum[32];
    int tid = threadIdx.x, lane = tid & 31, wid = tid >> 5;
    int v = (tid < nb) ? g_bsum[tid] : 0;
    int incl = v;
#pragma unroll
    for (int o = 1; o < 32; o <<= 1) {
        int t = __shfl_up_sync(0xffffffffu, incl, o);
        if (lane >= o) incl += t;
    }
    if (lane == 31) wsum[wid] = incl;
    __syncthreads();
    if (wid == 0) {
        int s = wsum[lane];
#pragma unroll
        for (int o = 1; o < 32; o <<= 1) {
            int t = __shfl_up_sync(0xffffffffu, s, o);
            if (lane >= o) s += t;
        }
        wsum[lane] = s;
    }
    __syncthreads();
    int wpre = wid ? wsum[wid - 1] : 0;
    int excl = wpre + incl - v;
    if (tid < nb) g_bsum[tid] = excl;
    if (tid == nb - 1) g_off[n] = excl + v;
}

__global__ void scanC_kernel(int n) {
    int i = blockIdx.x * 1024 + threadIdx.x;
    if (i < n) {
        int off = g_off[i] + g_bsum[blockIdx.x];
        g_off[i] = off;
        g_csr[off] = i;            // self loop in slot 0
        g_cur[i] = off + 1;
    }
}

__global__ void fill_edges_kernel(const int* __restrict__ ei, int e) {
    int i = blockIdx.x * blockDim.x + threadIdx.x;
    if (i < e) {
        int dst = ei[e + i];
        int pos = atomicAdd(&g_cur[dst], 1);
        g_csr[pos] = ei[i];                  // src
    }
}

// ---------- fp16 tensor-core GEMM (m16n8k16, fp32 accum) ----------
// BM=128, BN=64, BK=32, 256 threads (8 warps: 4x2, warp tile 32x32)
// AMODE 0: A fp32 row-major [M,K]. AMODE 1: jump-concat fp32. AMODE 2: A half2 row-major.
// EPI 0: none.  EPI 1: +bias.  EPI 2: +bias, BN, ELU.
// ATT 1: also compute g_as/g_ad (head = blockIdx.x; requires NC=256, grid.x=4)
// OUTH 1: C is half2 words (stride NC/2), packed column pairs; EPI must be 0.
template<int AMODE, int EPI, int ATT, int OUTH>
__global__ __launch_bounds__(256, 3)
void gemm_tc(const float* __restrict__ A, const float* __restrict__ B,
             const float* __restrict__ bias,
             const float* __restrict__ gamma, const float* __restrict__ beta,
             const float* __restrict__ mean, const float* __restrict__ var,
             const float* __restrict__ a_src, const float* __restrict__ a_dst,
             void* __restrict__ Cv, int M, int K, int NC)
{
    __shared__ __align__(16) unsigned As32[128 * 24];
    __shared__ __align__(16) unsigned Bs32[64 * 24];
    __shared__ float s_attw[128];
    __shared__ float s_att[128][4];

    int tid = threadIdx.x;
    int warp = tid >> 5, lane = tid & 31;
    int wm = (warp >> 1) * 32;
    int wn = (warp & 1) * 32;
    int row0 = blockIdx.y * 128, col0 = blockIdx.x * 64;
    int g = lane >> 2, q = lane & 3;

    if (ATT && tid < 128)
        s_attw[tid] = (tid < 64) ? a_src[blockIdx.x * 64 + tid]
                                 : a_dst[blockIdx.x * 64 + tid - 64];

    float c[2][4][4] = {};

    // A staging: thread -> (row ar+32i, 4 consecutive k at ac)
    int ar = tid >> 3;
    int ac = (tid & 7) * 4;
    int aP0 = ac >> 1;
    int apos0 = pairpos(aP0);
    int apos1 = pairpos(aP0 + 1);

    // B staging: thread -> (column bn, 8 consecutive k at bkg*8)
    int bn  = tid & 63;
    int bkg = tid >> 6;
    int ebn = 2 * ((bn >> 2) & 7);
    int bpos0 = pairpos(bkg * 4 + 0) ^ ebn;
    int bpos1 = pairpos(bkg * 4 + 1) ^ ebn;
    int bpos2 = pairpos(bkg * 4 + 2) ^ ebn;
    int bpos3 = pairpos(bkg * 4 + 3) ^ ebn;
    unsigned* brow = Bs32 + bn * 24;

    for (int k0 = 0; k0 < K; k0 += 32) {
#pragma unroll
        for (int i = 0; i < 4; i++) {
            int m = ar + i * 32;
            int gm = row0 + m;
            unsigned* arow = As32 + m * 24;
            if (AMODE == 2) {
                uint2 w = make_uint2(0u, 0u);
                if (gm < M)
                    w = *(const uint2*)((const unsigned*)A + (size_t)gm * (K >> 1) + ((k0 + ac) >> 1));
                arow[apos0] = w.x;
                arow[apos1] = w.y;
            } else {
                float4 v = make_float4(0.f, 0.f, 0.f, 0.f);
                if (gm < M) {
                    if (AMODE == 0)
                        v = *(const float4*)(A + (size_t)gm * K + k0 + ac);
                    else
                        v = *(const float4*)(A + (size_t)(k0 >> 6) * (NMAX * 64)
                                               + (size_t)gm * 64 + (k0 & 63) + ac);
                }
                arow[apos0] = pack_h2(v.x, v.y);
                arow[apos1] = pack_h2(v.z, v.w);
            }
        }
        {
            const float* bg = B + (size_t)(k0 + bkg * 8) * NC + col0 + bn;
            float f0 = bg[0];
            float f1 = bg[(size_t)NC];
            float f2 = bg[(size_t)2 * NC];
            float f3 = bg[(size_t)3 * NC];
            float f4 = bg[(size_t)4 * NC];
            float f5 = bg[(size_t)5 * NC];
            float f6 = bg[(size_t)6 * NC];
            float f7 = bg[(size_t)7 * NC];
            brow[bpos0] = pack_h2(f0, f1);
            brow[bpos1] = pack_h2(f2, f3);
            brow[bpos2] = pack_h2(f4, f5);
            brow[bpos3] = pack_h2(f6, f7);
        }
        __syncthreads();
#pragma unroll
        for (int ks = 0; ks < 2; ks++) {
            unsigned a[2][4], b[4][2];
#pragma unroll
            for (int mi = 0; mi < 2; mi++) {
                const unsigned* ap = As32 + (wm + mi * 16 + g) * 24 + ks * 8 + 2 * q;
                uint2 t0 = *(const uint2*)ap;
                uint2 t1 = *(const uint2*)(ap + 8 * 24);
                a[mi][0] = t0.x;
                a[mi][1] = t1.x;
                a[mi][2] = t0.y;
                a[mi][3] = t1.y;
            }
#pragma unroll
            for (int ni = 0; ni < 4; ni++) {
                int n2 = wn + ni * 8 + g;
                const unsigned* bp = Bs32 + n2 * 24
                                   + ((ks * 8 + 2 * q) ^ (2 * ((n2 >> 2) & 7)));
                uint2 tb = *(const uint2*)bp;
                b[ni][0] = tb.x;
                b[ni][1] = tb.y;
            }
#pragma unroll
            for (int mi = 0; mi < 2; mi++)
#pragma unroll
                for (int ni = 0; ni < 4; ni++)
                    mma_f16(c[mi][ni], a[mi], b[ni]);
        }
        __syncthreads();
    }

    // epilogue
    float* Cf = (float*)Cv;
    unsigned* Ch = (unsigned*)Cv;
    float ps[2][2] = {}, pd[2][2] = {};
#pragma unroll
    for (int mi = 0; mi < 2; mi++)
#pragma unroll
        for (int ni = 0; ni < 4; ni++) {
#pragma unroll
            for (int h8 = 0; h8 < 2; h8++) {
                int r = row0 + wm + mi * 16 + h8 * 8 + g;
                float vv[2];
#pragma unroll
                for (int cc = 0; cc < 2; cc++) {
                    int cloc = wn + ni * 8 + q * 2 + cc;
                    float v = c[mi][ni][h8 * 2 + cc];
                    if (ATT) {
                        ps[mi][h8] += v * s_attw[cloc];
                        pd[mi][h8] += v * s_attw[64 + cloc];
                    }
                    if (EPI >= 1) v += bias[col0 + cloc];
                    if (EPI == 2) {
                        int cidx = col0 + cloc;
                        v = (v - mean[cidx]) * rsqrtf(var[cidx] + BN_EPS) * gamma[cidx] + beta[cidx];
                        v = v > 0.f ? v : expm1f(v);
                    }
                    vv[cc] = v;
                }
                if (r < M) {
                    int cloc0 = wn + ni * 8 + q * 2;
                    if (OUTH) {
                        Ch[(size_t)r * (NC >> 1) + ((col0 + cloc0) >> 1)] = pack_h2(vv[0], vv[1]);
                    } else {
                        Cf[(size_t)r * NC + col0 + cloc0]     = vv[0];
                        Cf[(size_t)r * NC + col0 + cloc0 + 1] = vv[1];
                    }
                }
            }
        }

    if (ATT) {
#pragma unroll
        for (int mi = 0; mi < 2; mi++)
#pragma unroll
            for (int h8 = 0; h8 < 2; h8++) {
                float vs = ps[mi][h8], vd = pd[mi][h8];
                vs += __shfl_xor_sync(0xffffffffu, vs, 1);
                vs += __shfl_xor_sync(0xffffffffu, vs, 2);
                vd += __shfl_xor_sync(0xffffffffu, vd, 1);
                vd += __shfl_xor_sync(0xffffffffu, vd, 2);
                if (q == 0) {
                    int row = wm + mi * 16 + h8 * 8 + g;
                    s_att[row][(warp & 1) * 2 + 0] = vs;
                    s_att[row][(warp & 1) * 2 + 1] = vd;
                }
            }
        __syncthreads();
        if (tid < 128) {
            int r = row0 + tid;
            if (r < M) {
                g_as[(size_t)r * 4 + blockIdx.x] = s_att[tid][0] + s_att[tid][2];
                g_ad[(size_t)r * 4 + blockIdx.x] = s_att[tid][1] + s_att[tid][3];
            }
        }
    }
}

// ---- per-edge online-softmax aggregation core (R12 winner: shfl + prefetch) ----
#define AGG_EDGE_CORE()                                                         \
    float m0 = -1e30f, m1 = -1e30f, m2 = -1e30f, m3 = -1e30f;                   \
    float s0 = 0, s1 = 0, s2 = 0, s3 = 0;                                       \
    float acc[8] = {};                                                          \
    float adh = (lane < 4) ? g_ad[(size_t)w * 4 + lane] : 0.f;                  \
    int e0 = g_off[w], e1 = g_off[w + 1];                                       \
    int src_c = g_csr[e0];                                                      \
    float lr_c = (lane < 4) ? g_as[(size_t)src_c * 4 + lane] : 0.f;             \
    const unsigned* xr_c = g_xh + (size_t)src_c * 128;                          \
    unsigned xw_c0 = xr_c[lane];                                                \
    unsigned xw_c1 = xr_c[lane + 32];                                           \
    unsigned xw_c2 = xr_c[lane + 64];                                           \
    unsigned xw_c3 = xr_c[lane + 96];                                           \
    for (int e = e0; e < e1; e++) {                                             \
        int src_n; float lr_n;                                                  \
        unsigned xw_n0, xw_n1, xw_n2, xw_n3;                                    \
        if (e + 1 < e1) {                                                       \
            src_n = g_csr[e + 1];                                               \
            lr_n = (lane < 4) ? g_as[(size_t)src_n * 4 + lane] : 0.f;           \
            const unsigned* xr_n = g_xh + (size_t)src_n * 128;                  \
            xw_n0 = xr_n[lane];                                                 \
            xw_n1 = xr_n[lane + 32];                                            \
            xw_n2 = xr_n[lane + 64];                                            \
            xw_n3 = xr_n[lane + 96];                                            \
        }                                                                       \
        float l = 0.f;                                                          \
        if (lane < 4) {                                                         \
            float t = lr_c + adh;                                               \
            l = t > 0.f ? t : NEG * t;                                          \
        }                                                                       \
        float l0 = __shfl_sync(0xffffffffu, l, 0);                              \
        float l1 = __shfl_sync(0xffffffffu, l, 1);                              \
        float l2 = __shfl_sync(0xffffffffu, l, 2);                              \
        float l3 = __shfl_sync(0xffffffffu, l, 3);                              \
        float nm0 = fmaxf(m0, l0), nm1 = fmaxf(m1, l1);                         \
        float nm2 = fmaxf(m2, l2), nm3 = fmaxf(m3, l3);                         \
        float sc0 = __expf(m0 - nm0), sc1 = __expf(m1 - nm1);                   \
        float sc2 = __expf(m2 - nm2), sc3 = __expf(m3 - nm3);                   \
        float w0 = __expf(l0 - nm0), w1 = __expf(l1 - nm1);                     \
        float w2 = __expf(l2 - nm2), w3 = __expf(l3 - nm3);                     \
        s0 = s0 * sc0 + w0; s1 = s1 * sc1 + w1;                                 \
        s2 = s2 * sc2 + w2; s3 = s3 * sc3 + w3;                                 \
        m0 = nm0; m1 = nm1; m2 = nm2; m3 = nm3;                                 \
        float2 x0 = unpack_h2(xw_c0);                                           \
        float2 x1 = unpack_h2(xw_c1);                                           \
        float2 x2 = unpack_h2(xw_c2);                                           \
        float2 x3 = unpack_h2(xw_c3);                                           \
        acc[0] = acc[0] * sc0 + w0 * x0.x;                                      \
        acc[1] = acc[1] * sc0 + w0 * x0.y;                                      \
        acc[2] = acc[2] * sc1 + w1 * x1.x;                                      \
        acc[3] = acc[3] * sc1 + w1 * x1.y;                                      \
        acc[4] = acc[4] * sc2 + w2 * x2.x;                                      \
        acc[5] = acc[5] * sc2 + w2 * x2.y;                                      \
        acc[6] = acc[6] * sc3 + w3 * x3.x;                                      \
        acc[7] = acc[7] * sc3 + w3 * x3.y;                                      \
        if (e + 1 < e1) {                                                       \
            src_c = src_n; lr_c = lr_n;                                         \
            xw_c0 = xw_n0; xw_c1 = xw_n1; xw_c2 = xw_n2; xw_c3 = xw_n3;         \
        }                                                                       \
    }

// layer0: concat output (+bias), half2 out
__global__ void agg_concat_kernel(const float* __restrict__ bias, int n) {
    int w = blockIdx.x * (blockDim.x >> 5) + (threadIdx.x >> 5);
    int lane = threadIdx.x & 31;
    if (w >= n) return;
    AGG_EDGE_CORE();
    unsigned* o = g_agg + (size_t)w * 128;
    int cl = 2 * lane;
    o[lane]      = pack_h2(acc[0] / s0 + bias[cl],       acc[1] / s0 + bias[cl + 1]);
    o[lane + 32] = pack_h2(acc[2] / s1 + bias[64 + cl],  acc[3] / s1 + bias[64 + cl + 1]);
    o[lane + 64] = pack_h2(acc[4] / s2 + bias[128 + cl], acc[5] / s2 + bias[128 + cl + 1]);
    o[lane + 96] = pack_h2(acc[6] / s3 + bias[192 + cl], acc[7] / s3 + bias[192 + cl + 1]);
}

// layers 1/2: mean over heads + bias + BN + ELU + residual (fp32 out)
__global__ void agg_mean_kernel(const float* __restrict__ bias,
                                const float* __restrict__ gamma, const float* __restrict__ beta,
                                const float* __restrict__ mean,  const float* __restrict__ var,
                                const float* __restrict__ h_in, float* __restrict__ h_out, int n) {
    int w = blockIdx.x * (blockDim.x >> 5) + (threadIdx.x >> 5);
    int lane = threadIdx.x & 31;
    if (w >= n) return;
    AGG_EDGE_CORE();
    float i0 = 1.f / s0, i1 = 1.f / s1, i2 = 1.f / s2, i3 = 1.f / s3;
    int c0 = 2 * lane, c1 = 2 * lane + 1;
    float v0 = 0.25f * (acc[0] * i0 + acc[2] * i1 + acc[4] * i2 + acc[6] * i3) + bias[c0];
    float v1 = 0.25f * (acc[1] * i0 + acc[3] * i1 + acc[5] * i2 + acc[7] * i3) + bias[c1];
    v0 = (v0 - mean[c0]) * rsqrtf(var[c0] + BN_EPS) * gamma[c0] + beta[c0];
    v1 = (v1 - mean[c1]) * rsqrtf(var[c1] + BN_EPS) * gamma[c1] + beta[c1];
    v0 = v0 > 0.f ? v0 : expm1f(v0);
    v1 = v1 > 0.f ? v1 : expm1f(v1);
    size_t o = (size_t)w * 64;
    float2 hin = *(const float2*)(h_in + o + c0);
    float2 res = make_float2(v0 + hin.x, v1 + hin.y);
    *(float2*)(h_out + o + c0) = res;
}

// ---- fused attentional pooling + classifier: one block per graph (batch sorted)
__global__ __launch_bounds__(256)
void pool_cls_kernel(const float* __restrict__ attW, const int* __restrict__ batch,
                     const float* __restrict__ W1, const float* __restrict__ b1,
                     const float* __restrict__ W2, const float* __restrict__ b2,
                     float* __restrict__ out, int n)
{
    int gidx = blockIdx.x;
    int tid = threadIdx.x, lane = tid & 31, warp = tid >> 5;
    __shared__ float sW[64];
    __shared__ float rmax[8], rsum[8];
    __shared__ float shg[64];
    __shared__ float shid[32];
    __shared__ int sbnd[2];

    if (tid < 64) { sW[tid] = attW[tid]; shg[tid] = 0.f; }
    if (tid == 0) {
        int lo = 0, hi = n;
        while (lo < hi) { int m = (lo + hi) >> 1; if (batch[m] < gidx) lo = m + 1; else hi = m; }
        sbnd[0] = lo;
        int l2 = lo, h2 = n;
        while (l2 < h2) { int m = (l2 + h2) >> 1; if (batch[m] <= gidx) l2 = m + 1; else h2 = m; }
        sbnd[1] = l2;
    }
    __syncthreads();
    int lo = sbnd[0], hi = sbnd[1];

    float mx = -1e30f;
    for (int i = lo + warp; i < hi; i += 8) {
        const float* hr = g_hj + (size_t)i * 64;
        float p = hr[lane] * sW[lane] + hr[lane + 32] * sW[lane + 32];
#pragma unroll
        for (int o = 16; o > 0; o >>= 1) p += __shfl_xor_sync(0xffffffffu, p, o);
        mx = fmaxf(mx, p);
    }
    if (lane == 0) rmax[warp] = mx;
    __syncthreads();
    float bmax = -1e30f;
#pragma unroll
    for (int wq = 0; wq < 8; wq++) bmax = fmaxf(bmax, rmax[wq]);

    float a0 = 0.f, a1 = 0.f, se = 0.f;
    for (int i = lo + warp; i < hi; i += 8) {
        const float* hr = g_hj + (size_t)i * 64;
        float h0 = hr[lane], h1 = hr[lane + 32];
        float p = h0 * sW[lane] + h1 * sW[lane + 32];
#pragma unroll
        for (int o = 16; o > 0; o >>= 1) p += __shfl_xor_sync(0xffffffffu, p, o);
        float ev = __expf(p - bmax);
        a0 += ev * h0; a1 += ev * h1; se += ev;
    }
    if (lane == 0) rsum[warp] = se;
    atomicAdd(&shg[lane], a0);
    atomicAdd(&shg[lane + 32], a1);
    __syncthreads();

    float setot = 0.f;
#pragma unroll
    for (int wq = 0; wq < 8; wq++) setot += rsum[wq];
    float inv = (setot > 0.f) ? 1.f / setot : 0.f;

    if (tid < 32) {
        float acc = b1[tid];
        for (int cc = 0; cc < 64; cc++) acc += shg[cc] * inv * W1[cc * 32 + tid];
        shid[tid] = acc > 0.f ? acc : 0.f;
    }
    __syncthreads();
    if (tid < 2) {
        float o = b2[tid];
#pragma unroll
        for (int j = 0; j < 32; j++) o += shid[j] * W2[j * 2 + tid];
        out[gidx * 2 + tid] = o;
    }
}

// ---------------- host ----------------
extern "C" void kernel_launch(void* const* d_in, const int* in_sizes, int n_in,
                              void* d_out, int out_size) {
    const float* x        = (const float*)d_in[0];
    const int*   ei       = (const int*)d_in[1];
    const int*   batch    = (const int*)d_in[2];
    const float* conv0_W  = (const float*)d_in[3];
    const float* c0_asrc  = (const float*)d_in[4];
    const float* c0_adst  = (const float*)d_in[5];
    const float* c0_bias  = (const float*)d_in[6];
    const float* pre0_W   = (const float*)d_in[7];
    const float* pre0_b   = (const float*)d_in[8];
    const float* convs_W  = (const float*)d_in[9];
    const float* cs_asrc  = (const float*)d_in[10];
    const float* cs_adst  = (const float*)d_in[11];
    const float* cs_bias  = (const float*)d_in[12];
    const float* bn_g     = (const float*)d_in[13];
    const float* bn_b     = (const float*)d_in[14];
    const float* bn_m     = (const float*)d_in[15];
    const float* bn_v     = (const float*)d_in[16];
    const float* jump_W   = (const float*)d_in[17];
    const float* jump_b   = (const float*)d_in[18];
    const float* att_W    = (const float*)d_in[19];
    const float* cls_W1   = (const float*)d_in[21];
    const float* cls_b1   = (const float*)d_in[22];
    const float* cls_W2   = (const float*)d_in[23];
    const float* cls_b2   = (const float*)d_in[24];

    int n = in_sizes[0] / 128;
    int e = in_sizes[1] / 2;

    unsigned *p_xh, *p_agg;
    float *p_rep, *p_hj;
    int *p_deg;
    cudaGetSymbolAddress((void**)&p_xh,  g_xh);
    cudaGetSymbolAddress((void**)&p_agg, g_agg);
    cudaGetSymbolAddress((void**)&p_rep, g_rep);
    cudaGetSymbolAddress((void**)&p_hj,  g_hj);
    cudaGetSymbolAddress((void**)&p_deg, g_deg);

    // side stream + fork/join events (created once; stream/event objects are
    // not device-memory allocations)
    static cudaStream_t s2 = nullptr;
    static cudaEvent_t evFork = nullptr, evJoin = nullptr;
    if (!s2) {
        cudaStreamCreateWithFlags(&s2, cudaStreamNonBlocking);
        cudaEventCreateWithFlags(&evFork, cudaEventDisableTiming);
        cudaEventCreateWithFlags(&evJoin, cudaEventDisableTiming);
    }

    const int T = 256;
    int ebN  = (e + T - 1) / T;
    int wb   = (n + 7) / 8;
    int mg   = (n + 127) / 128;
    int nb2  = (n + 1023) / 1024;

    // ---- fork: CSR build on s2 runs concurrently with conv0 GEMM on main ----
    cudaEventRecord(evFork, 0);
    cudaStreamWaitEvent(s2, evFork, 0);

    cudaMemsetAsync(p_deg, 0, (size_t)n * sizeof(int), s2);
    count_kernel<<<ebN, T, 0, s2>>>(ei, e);
    scanA_kernel<<<nb2, 1024, 0, s2>>>(n);
    scanB_kernel<<<1, 1024, 0, s2>>>(nb2, n);
    scanC_kernel<<<nb2, 1024, 0, s2>>>(n);
    fill_edges_kernel<<<ebN, T, 0, s2>>>(ei, e);
    cudaEventRecord(evJoin, s2);

    // main stream: layer-0 GEMM (independent of CSR)
    gemm_tc<0,0,1,1><<<dim3(4, mg), 256>>>(x, conv0_W, nullptr, nullptr, nullptr,
                                           nullptr, nullptr, c0_asrc, c0_adst,
                                           p_xh, n, 128, 256);

    // join: aggregation needs both CSR and g_xh
    cudaStreamWaitEvent(0, evJoin, 0);

    // ---- layer 0 aggregation (concat, half2 out) + pre0 (half A, bias+BN+ELU) ----
    agg_concat_kernel<<<wb, T>>>(c0_bias, n);
    gemm_tc<2,2,0,0><<<dim3(1, mg), 256>>>((const float*)p_agg, pre0_W, pre0_b, bn_g, bn_b,
                                           bn_m, bn_v, nullptr, nullptr,
                                           p_rep, n, 256, 64);

    // ---- layers 1,2 (mean heads, fused BN/ELU/residual in agg) ----
    for (int i = 0; i < 2; i++) {
        const float* rin  = p_rep + (size_t)i * NMAX * 64;
        float*       rout = p_rep + (size_t)(i + 1) * NMAX * 64;
        gemm_tc<0,0,1,1><<<dim3(4, mg), 256>>>(rin, convs_W + (size_t)i * 64 * 256,
                                               nullptr, nullptr, nullptr, nullptr, nullptr,
                                               cs_asrc + i * 256, cs_adst + i * 256,
                                               p_xh, n, 64, 256);
        agg_mean_kernel<<<wb, T>>>(cs_bias + i * 64,
                                   bn_g + (i + 1) * 64, bn_b + (i + 1) * 64,
                                   bn_m + (i + 1) * 64, bn_v + (i + 1) * 64,
                                   rin, rout, n);
    }

    // ---- jumping knowledge GEMM reads rep[] directly (AMODE=1), fused bias ----
    gemm_tc<1,1,0,0><<<dim3(1, mg), 256>>>(p_rep, jump_W, jump_b, nullptr, nullptr,
                                           nullptr, nullptr, nullptr, nullptr,
                                           p_hj, n, 192, 64);

    // ---- fused pooling + classifier ----
    pool_cls_kernel<<<GRAPHS, 256>>>(att_W, batch, cls_W1, cls_b1, cls_W2, cls_b2,
                                     (float*)d_out, n);
}

// round 16
// speedup vs baseline: 1.1056x; 1.0215x over previous
#include <cuda_runtime.h>
#include <cuda_fp16.h>
#include <math.h>

#define NMAX   50000
#define HEADS  4
#define HID    64
#define GRAPHS 64
#define NEG    0.2f
#define BN_EPS 1e-5f
#define EMAXT  460000

// ---------------- scratch (device globals; no allocations allowed) ----------
// half2 words: word j of a row = channels (2j, 2j+1)
__device__ __align__(16) unsigned g_xh   [NMAX * 128];  // projected features
__device__ __align__(16) unsigned g_agg  [NMAX * 128];  // layer0 agg (half2)
__device__ __align__(16) unsigned g_xhalf[NMAX * 64];   // x converted to half2
__device__ __align__(16) unsigned g_reph [3 * NMAX * 32]; // rep half2 copies
__device__ __align__(16) unsigned g_Bimg [70656];       // pre-swizzled B images
__device__ __align__(16) float g_as [NMAX * 4];
__device__ __align__(16) float g_ad [NMAX * 4];
__device__ float g_rep[3 * NMAX * 64];   // reps fp32 (residual + BN path)
__device__ float g_hj [NMAX * 64];       // jump output (fp32)
__device__ int   g_deg[NMAX + 1];
__device__ int   g_off[NMAX + 1];
__device__ int   g_cur[NMAX];
__device__ int   g_csr[EMAXT];
__device__ int   g_bsum[128];

// ---------------- helpers ----------------
__device__ __forceinline__ unsigned pack_h2(float lo, float hi) {
    __half2 h = __floats2half2_rn(lo, hi);   // low 16 bits = lo
    return *reinterpret_cast<unsigned*>(&h);
}
__device__ __forceinline__ float2 unpack_h2(unsigned u) {
    return __half22float2(*reinterpret_cast<__half2*>(&u));
}
__device__ __forceinline__ void mma_f16(float c[4], const unsigned a[4], const unsigned b[2]) {
    asm volatile("mma.sync.aligned.m16n8k16.row.col.f32.f16.f16.f32 "
                 "{%0,%1,%2,%3},{%4,%5,%6,%7},{%8,%9},{%0,%1,%2,%3};"
                 : "+f"(c[0]), "+f"(c[1]), "+f"(c[2]), "+f"(c[3])
                 : "r"(a[0]), "r"(a[1]), "r"(a[2]), "r"(a[3]), "r"(b[0]), "r"(b[1]));
}
__device__ __forceinline__ int pairpos(int P) {
    return (P & 8) + 2 * (P & 3) + ((P >> 2) & 1);
}
__device__ __forceinline__ void cpa16(unsigned* smem, const void* g, bool p) {
    unsigned s = (unsigned)__cvta_generic_to_shared(smem);
    int bytes = p ? 16 : 0;
    asm volatile("cp.async.ca.shared.global [%0], [%1], 16, %2;" :: "r"(s), "l"(g), "r"(bytes));
}
__device__ __forceinline__ void cpa4(unsigned* smem, const void* g, bool p) {
    unsigned s = (unsigned)__cvta_generic_to_shared(smem);
    int bytes = p ? 4 : 0;
    asm volatile("cp.async.ca.shared.global [%0], [%1], 4, %2;" :: "r"(s), "l"(g), "r"(bytes));
}
#define CP_COMMIT() asm volatile("cp.async.commit_group;")
#define CP_WAIT1()  asm volatile("cp.async.wait_group 1;")
#define CP_WAIT0()  asm volatile("cp.async.wait_group 0;")

// ---------------- input conversion ----------------
__global__ void cvt_half_kernel(const float* __restrict__ in, unsigned* __restrict__ out,
                                int nwords) {
    int i = blockIdx.x * blockDim.x + threadIdx.x;
    if (i < nwords) {
        float2 v = *(const float2*)(in + 2 * i);
        out[i] = pack_h2(v.x, v.y);
    }
}

// pre-transform the 5 weight matrices into swizzled smem-image layout.
// Image layout per (colblock*nk + t): 64 cols x 24 words; replicates old staging.
__global__ void prep_B_kernel(const float* __restrict__ c0W, const float* __restrict__ p0W,
                              const float* __restrict__ csW, const float* __restrict__ jW) {
    int b = blockIdx.x, tid = threadIdx.x;
    const float* src; int NC, nk, idx, imgoff;
    if (b < 16)      { src = c0W;            NC = 256; nk = 4; idx = b;      imgoff = 0; }
    else if (b < 24) { src = p0W;            NC = 64;  nk = 8; idx = b - 16; imgoff = 24576; }
    else if (b < 32) { src = csW;            NC = 256; nk = 2; idx = b - 24; imgoff = 36864; }
    else if (b < 40) { src = csW + 64 * 256; NC = 256; nk = 2; idx = b - 32; imgoff = 49152; }
    else             { src = jW;             NC = 64;  nk = 6; idx = b - 40; imgoff = 61440; }
    int cb = idx / nk, t = idx % nk;
    int bn = tid & 63, bkg = tid >> 6;
    int ebn = 2 * ((bn >> 2) & 7);
    int k0 = t * 32, col = cb * 64 + bn;
    const float* bg = src + (size_t)(k0 + bkg * 8) * NC + col;
    unsigned* out = g_Bimg + imgoff + (size_t)idx * 1536 + bn * 24;
#pragma unroll
    for (int j = 0; j < 4; j++) {
        float flo = bg[(size_t)(2 * j) * NC];
        float fhi = bg[(size_t)(2 * j + 1) * NC];
        out[pairpos(bkg * 4 + j) ^ ebn] = pack_h2(flo, fhi);
    }
}

// ---------------- CSR build ----------------
__global__ void count_kernel(const int* __restrict__ ei, int e) {
    int i = blockIdx.x * blockDim.x + threadIdx.x;
    if (i < e) atomicAdd(&g_deg[ei[e + i]], 1);   // dst row is second
}

__global__ void scanA_kernel(int n) {
    __shared__ int wsum[32];
    int tid = threadIdx.x, lane = tid & 31, wid = tid >> 5;
    int i = blockIdx.x * 1024 + tid;
    int v = (i < n) ? g_deg[i] + 1 : 0;       // +1 = self loop
    int incl = v;
#pragma unroll
    for (int o = 1; o < 32; o <<= 1) {
        int t = __shfl_up_sync(0xffffffffu, incl, o);
        if (lane >= o) incl += t;
    }
    if (lane == 31) wsum[wid] = incl;
    __syncthreads();
    if (wid == 0) {
        int s = wsum[lane];
#pragma unroll
        for (int o = 1; o < 32; o <<= 1) {
            int t = __shfl_up_sync(0xffffffffu, s, o);
            if (lane >= o) s += t;
        }
        wsum[lane] = s;
    }
    __syncthreads();
    int wpre = wid ? wsum[wid - 1] : 0;
    if (i < n) g_off[i] = wpre + incl - v;
    if (tid == 0) g_bsum[blockIdx.x] = wsum[31];
}

__global__ void scanB_kernel(int nb, int n) {
    __shared__ int wsum[32];
    int tid = threadIdx.x, lane = tid & 31, wid = tid >> 5;
    int v = (tid < nb) ? g_bsum[tid] : 0;
    int incl = v;
#pragma unroll
    for (int o = 1; o < 32; o <<= 1) {
        int t = __shfl_up_sync(0xffffffffu, incl, o);
        if (lane >= o) incl += t;
    }
    if (lane == 31) wsum[wid] = incl;
    __syncthreads();
    if (wid == 0) {
        int s = wsum[lane];
#pragma unroll
        for (int o = 1; o < 32; o <<= 1) {
            int t = __shfl_up_sync(0xffffffffu, s, o);
            if (lane >= o) s += t;
        }
        wsum[lane] = s;
    }
    __syncthreads();
    int wpre = wid ? wsum[wid - 1] : 0;
    int excl = wpre + incl - v;
    if (tid < nb) g_bsum[tid] = excl;
    if (tid == nb - 1) g_off[n] = excl + v;
}

__global__ void scanC_kernel(int n) {
    int i = blockIdx.x * 1024 + threadIdx.x;
    if (i < n) {
        int off = g_off[i] + g_bsum[blockIdx.x];
        g_off[i] = off;
        g_csr[off] = i;            // self loop in slot 0
        g_cur[i] = off + 1;
    }
}

__global__ void fill_edges_kernel(const int* __restrict__ ei, int e) {
    int i = blockIdx.x * blockDim.x + threadIdx.x;
    if (i < e) {
        int dst = ei[e + i];
        int pos = atomicAdd(&g_cur[dst], 1);
        g_csr[pos] = ei[i];                  // src
    }
}

// ---------- fp16 tensor-core GEMM, cp.async 2-stage, 3 CTAs/SM ----------
// BM=128, BN=64, BK=32, 256 threads (8 warps: 4x2, warp tile 32x32)
// All inputs half2. AMODE 0: A2 row-major (K/2 words/row). AMODE 1: jump-concat
//   over g_reph layers (layer = k>>6, 32 words/row/layer).
// B comes from a pre-swizzled image: tile (blockIdx.x*nk + t) * 1536 words.
// EPI 0: none. 1: +bias. 2: +bias,BN,ELU.  ATT: attention coeffs.  OUTH: half C.
// DUALH: also write half2 copy of C to g_reph layer 0 (pre0 path).
template<int AMODE, int EPI, int ATT, int OUTH, int DUALH>
__global__ __launch_bounds__(256, 3)
void gemm_tc(const unsigned* __restrict__ A2, const unsigned* __restrict__ Bimg,
             const float* __restrict__ bias,
             const float* __restrict__ gamma, const float* __restrict__ beta,
             const float* __restrict__ mean, const float* __restrict__ var,
             const float* __restrict__ a_src, const float* __restrict__ a_dst,
             void* __restrict__ Cv, int M, int K, int NC)
{
    __shared__ __align__(16) unsigned As32[2][128 * 24];
    __shared__ __align__(16) unsigned Bs32[2][64 * 24];
    __shared__ float s_attw[128];
    __shared__ float s_att[128][4];

    int tid = threadIdx.x;
    int warp = tid >> 5, lane = tid & 31;
    int wm = (warp >> 1) * 32;
    int wn = (warp & 1) * 32;
    int row0 = blockIdx.y * 128, col0 = blockIdx.x * 64;
    int g = lane >> 2, q = lane & 3;
    int nk = K >> 5;

    if (ATT && tid < 128)
        s_attw[tid] = (tid < 64) ? a_src[blockIdx.x * 64 + tid]
                                 : a_dst[blockIdx.x * 64 + tid - 64];

    float c[2][4][4] = {};

    // A staging geometry: thread -> (row ar+32i, 4 consecutive k at ac)
    int ar = tid >> 3;
    int ac = (tid & 7) * 4;
    int aP0 = ac >> 1;
    int apos0 = pairpos(aP0);
    int apos1 = pairpos(aP0 + 1);

    auto load_tile = [&](int t) {
        unsigned* As_ = As32[t & 1];
        unsigned* Bs_ = Bs32[t & 1];
        int k0 = t << 5;
#pragma unroll
        for (int i = 0; i < 4; i++) {
            int m = ar + i * 32;
            int gm = row0 + m;
            const unsigned* src;
            if (AMODE == 0) {
                src = A2 + (size_t)gm * (K >> 1) + ((k0 + ac) >> 1);
            } else {
                int layer = k0 >> 6;
                src = A2 + (size_t)layer * (NMAX * 32) + (size_t)gm * 32
                    + (((k0 & 63) + ac) >> 1);
            }
            bool p = gm < M;
            unsigned* arow = As_ + m * 24;
            cpa4(arow + apos0, src, p);
            cpa4(arow + apos1, src + 1, p);
        }
        const unsigned* img = Bimg + (size_t)(blockIdx.x * nk + t) * 1536;
        cpa16(Bs_ + (tid << 2), img + (tid << 2), true);
        if (tid < 128) cpa16(Bs_ + 1024 + (tid << 2), img + 1024 + (tid << 2), true);
        CP_COMMIT();
    };

    load_tile(0);
    for (int t = 0; t < nk; t++) {
        if (t + 1 < nk) { load_tile(t + 1); CP_WAIT1(); }
        else            { CP_WAIT0(); }
        __syncthreads();
        const unsigned* As_ = As32[t & 1];
        const unsigned* Bs_ = Bs32[t & 1];
#pragma unroll
        for (int ks = 0; ks < 2; ks++) {
            unsigned a[2][4], b[4][2];
#pragma unroll
            for (int mi = 0; mi < 2; mi++) {
                const unsigned* ap = As_ + (wm + mi * 16 + g) * 24 + ks * 8 + 2 * q;
                uint2 t0 = *(const uint2*)ap;
                uint2 t1 = *(const uint2*)(ap + 8 * 24);
                a[mi][0] = t0.x;
                a[mi][1] = t1.x;
                a[mi][2] = t0.y;
                a[mi][3] = t1.y;
            }
#pragma unroll
            for (int ni = 0; ni < 4; ni++) {
                int n2 = wn + ni * 8 + g;
                const unsigned* bp = Bs_ + n2 * 24
                                   + ((ks * 8 + 2 * q) ^ (2 * ((n2 >> 2) & 7)));
                uint2 tb = *(const uint2*)bp;
                b[ni][0] = tb.x;
                b[ni][1] = tb.y;
            }
#pragma unroll
            for (int mi = 0; mi < 2; mi++)
#pragma unroll
                for (int ni = 0; ni < 4; ni++)
                    mma_f16(c[mi][ni], a[mi], b[ni]);
        }
        __syncthreads();
    }

    // epilogue
    float* Cf = (float*)Cv;
    unsigned* Ch = (unsigned*)Cv;
    float ps[2][2] = {}, pd[2][2] = {};
#pragma unroll
    for (int mi = 0; mi < 2; mi++)
#pragma unroll
        for (int ni = 0; ni < 4; ni++) {
#pragma unroll
            for (int h8 = 0; h8 < 2; h8++) {
                int r = row0 + wm + mi * 16 + h8 * 8 + g;
                float vv[2];
#pragma unroll
                for (int cc = 0; cc < 2; cc++) {
                    int cloc = wn + ni * 8 + q * 2 + cc;
                    float v = c[mi][ni][h8 * 2 + cc];
                    if (ATT) {
                        ps[mi][h8] += v * s_attw[cloc];
                        pd[mi][h8] += v * s_attw[64 + cloc];
                    }
                    if (EPI >= 1) v += bias[col0 + cloc];
                    if (EPI == 2) {
                        int cidx = col0 + cloc;
                        v = (v - mean[cidx]) * rsqrtf(var[cidx] + BN_EPS) * gamma[cidx] + beta[cidx];
                        v = v > 0.f ? v : expm1f(v);
                    }
                    vv[cc] = v;
                }
                if (r < M) {
                    int cloc0 = wn + ni * 8 + q * 2;
                    if (OUTH) {
                        Ch[(size_t)r * (NC >> 1) + ((col0 + cloc0) >> 1)] = pack_h2(vv[0], vv[1]);
                    } else {
                        Cf[(size_t)r * NC + col0 + cloc0]     = vv[0];
                        Cf[(size_t)r * NC + col0 + cloc0 + 1] = vv[1];
                    }
                    if (DUALH)
                        g_reph[(size_t)r * 32 + ((col0 + cloc0) >> 1)] = pack_h2(vv[0], vv[1]);
                }
            }
        }

    if (ATT) {
#pragma unroll
        for (int mi = 0; mi < 2; mi++)
#pragma unroll
            for (int h8 = 0; h8 < 2; h8++) {
                float vs = ps[mi][h8], vd = pd[mi][h8];
                vs += __shfl_xor_sync(0xffffffffu, vs, 1);
                vs += __shfl_xor_sync(0xffffffffu, vs, 2);
                vd += __shfl_xor_sync(0xffffffffu, vd, 1);
                vd += __shfl_xor_sync(0xffffffffu, vd, 2);
                if (q == 0) {
                    int row = wm + mi * 16 + h8 * 8 + g;
                    s_att[row][(warp & 1) * 2 + 0] = vs;
                    s_att[row][(warp & 1) * 2 + 1] = vd;
                }
            }
        __syncthreads();
        if (tid < 128) {
            int r = row0 + tid;
            if (r < M) {
                g_as[(size_t)r * 4 + blockIdx.x] = s_att[tid][0] + s_att[tid][2];
                g_ad[(size_t)r * 4 + blockIdx.x] = s_att[tid][1] + s_att[tid][3];
            }
        }
    }
}

// ---- per-edge online-softmax aggregation core (R12 winner: shfl + prefetch) ----
#define AGG_EDGE_CORE()                                                         \
    float m0 = -1e30f, m1 = -1e30f, m2 = -1e30f, m3 = -1e30f;                   \
    float s0 = 0, s1 = 0, s2 = 0, s3 = 0;                                       \
    float acc[8] = {};                                                          \
    float adh = (lane < 4) ? g_ad[(size_t)w * 4 + lane] : 0.f;                  \
    int e0 = g_off[w], e1 = g_off[w + 1];                                       \
    int src_c = g_csr[e0];                                                      \
    float lr_c = (lane < 4) ? g_as[(size_t)src_c * 4 + lane] : 0.f;             \
    const unsigned* xr_c = g_xh + (size_t)src_c * 128;                          \
    unsigned xw_c0 = xr_c[lane];                                                \
    unsigned xw_c1 = xr_c[lane + 32];                                           \
    unsigned xw_c2 = xr_c[lane + 64];                                           \
    unsigned xw_c3 = xr_c[lane + 96];                                           \
    for (int e = e0; e < e1; e++) {                                             \
        int src_n; float lr_n;                                                  \
        unsigned xw_n0, xw_n1, xw_n2, xw_n3;                                    \
        if (e + 1 < e1) {                                                       \
            src_n = g_csr[e + 1];                                               \
            lr_n = (lane < 4) ? g_as[(size_t)src_n * 4 + lane] : 0.f;           \
            const unsigned* xr_n = g_xh + (size_t)src_n * 128;                  \
            xw_n0 = xr_n[lane];                                                 \
            xw_n1 = xr_n[lane + 32];                                            \
            xw_n2 = xr_n[lane + 64];                                            \
            xw_n3 = xr_n[lane + 96];                                            \
        }                                                                       \
        float l = 0.f;                                                          \
        if (lane < 4) {                                                         \
            float t = lr_c + adh;                                               \
            l = t > 0.f ? t : NEG * t;                                          \
        }                                                                       \
        float l0 = __shfl_sync(0xffffffffu, l, 0);                              \
        float l1 = __shfl_sync(0xffffffffu, l, 1);                              \
        float l2 = __shfl_sync(0xffffffffu, l, 2);                              \
        float l3 = __shfl_sync(0xffffffffu, l, 3);                              \
        float nm0 = fmaxf(m0, l0), nm1 = fmaxf(m1, l1);                         \
        float nm2 = fmaxf(m2, l2), nm3 = fmaxf(m3, l3);                         \
        float sc0 = __expf(m0 - nm0), sc1 = __expf(m1 - nm1);                   \
        float sc2 = __expf(m2 - nm2), sc3 = __expf(m3 - nm3);                   \
        float w0 = __expf(l0 - nm0), w1 = __expf(l1 - nm1);                     \
        float w2 = __expf(l2 - nm2), w3 = __expf(l3 - nm3);                     \
        s0 = s0 * sc0 + w0; s1 = s1 * sc1 + w1;                                 \
        s2 = s2 * sc2 + w2; s3 = s3 * sc3 + w3;                                 \
        m0 = nm0; m1 = nm1; m2 = nm2; m3 = nm3;                                 \
        float2 x0 = unpack_h2(xw_c0);                                           \
        float2 x1 = unpack_h2(xw_c1);                                           \
        float2 x2 = unpack_h2(xw_c2);                                           \
        float2 x3 = unpack_h2(xw_c3);                                           \
        acc[0] = acc[0] * sc0 + w0 * x0.x;                                      \
        acc[1] = acc[1] * sc0 + w0 * x0.y;                                      \
        acc[2] = acc[2] * sc1 + w1 * x1.x;                                      \
        acc[3] = acc[3] * sc1 + w1 * x1.y;                                      \
        acc[4] = acc[4] * sc2 + w2 * x2.x;                                      \
        acc[5] = acc[5] * sc2 + w2 * x2.y;                                      \
        acc[6] = acc[6] * sc3 + w3 * x3.x;                                      \
        acc[7] = acc[7] * sc3 + w3 * x3.y;                                      \
        if (e + 1 < e1) {                                                       \
            src_c = src_n; lr_c = lr_n;                                         \
            xw_c0 = xw_n0; xw_c1 = xw_n1; xw_c2 = xw_n2; xw_c3 = xw_n3;         \
        }                                                                       \
    }

// layer0: concat output (+bias), half2 out
__global__ void agg_concat_kernel(const float* __restrict__ bias, int n) {
    int w = blockIdx.x * (blockDim.x >> 5) + (threadIdx.x >> 5);
    int lane = threadIdx.x & 31;
    if (w >= n) return;
    AGG_EDGE_CORE();
    unsigned* o = g_agg + (size_t)w * 128;
    int cl = 2 * lane;
    o[lane]      = pack_h2(acc[0] / s0 + bias[cl],       acc[1] / s0 + bias[cl + 1]);
    o[lane + 32] = pack_h2(acc[2] / s1 + bias[64 + cl],  acc[3] / s1 + bias[64 + cl + 1]);
    o[lane + 64] = pack_h2(acc[4] / s2 + bias[128 + cl], acc[5] / s2 + bias[128 + cl + 1]);
    o[lane + 96] = pack_h2(acc[6] / s3 + bias[192 + cl], acc[7] / s3 + bias[192 + cl + 1]);
}

// layers 1/2: mean heads + bias + BN + ELU + residual; fp32 out + half2 dual copy
__global__ void agg_mean_kernel(const float* __restrict__ bias,
                                const float* __restrict__ gamma, const float* __restrict__ beta,
                                const float* __restrict__ mean,  const float* __restrict__ var,
                                const float* __restrict__ h_in, float* __restrict__ h_out,
                                unsigned* __restrict__ h_out_h, int n) {
    int w = blockIdx.x * (blockDim.x >> 5) + (threadIdx.x >> 5);
    int lane = threadIdx.x & 31;
    if (w >= n) return;
    AGG_EDGE_CORE();
    float i0 = 1.f / s0, i1 = 1.f / s1, i2 = 1.f / s2, i3 = 1.f / s3;
    int c0 = 2 * lane, c1 = 2 * lane + 1;
    float v0 = 0.25f * (acc[0] * i0 + acc[2] * i1 + acc[4] * i2 + acc[6] * i3) + bias[c0];
    float v1 = 0.25f * (acc[1] * i0 + acc[3] * i1 + acc[5] * i2 + acc[7] * i3) + bias[c1];
    v0 = (v0 - mean[c0]) * rsqrtf(var[c0] + BN_EPS) * gamma[c0] + beta[c0];
    v1 = (v1 - mean[c1]) * rsqrtf(var[c1] + BN_EPS) * gamma[c1] + beta[c1];
    v0 = v0 > 0.f ? v0 : expm1f(v0);
    v1 = v1 > 0.f ? v1 : expm1f(v1);
    size_t o = (size_t)w * 64;
    float2 hin = *(const float2*)(h_in + o + c0);
    float2 res = make_float2(v0 + hin.x, v1 + hin.y);
    *(float2*)(h_out + o + c0) = res;
    h_out_h[(size_t)w * 32 + lane] = pack_h2(res.x, res.y);
}

// ---- fused attentional pooling + classifier: one block per graph (batch sorted)
__global__ __launch_bounds__(256)
void pool_cls_kernel(const float* __restrict__ attW, const int* __restrict__ batch,
                     const float* __restrict__ W1, const float* __restrict__ b1,
                     const float* __restrict__ W2, const float* __restrict__ b2,
                     float* __restrict__ out, int n)
{
    int gidx = blockIdx.x;
    int tid = threadIdx.x, lane = tid & 31, warp = tid >> 5;
    __shared__ float sW[64];
    __shared__ float rmax[8], rsum[8];
    __shared__ float shg[64];
    __shared__ float shid[32];
    __shared__ int sbnd[2];

    if (tid < 64) { sW[tid] = attW[tid]; shg[tid] = 0.f; }
    if (tid == 0) {
        int lo = 0, hi = n;
        while (lo < hi) { int m = (lo + hi) >> 1; if (batch[m] < gidx) lo = m + 1; else hi = m; }
        sbnd[0] = lo;
        int l2 = lo, h2 = n;
        while (l2 < h2) { int m = (l2 + h2) >> 1; if (batch[m] <= gidx) l2 = m + 1; else h2 = m; }
        sbnd[1] = l2;
    }
    __syncthreads();
    int lo = sbnd[0], hi = sbnd[1];

    float mx = -1e30f;
    for (int i = lo + warp; i < hi; i += 8) {
        const float* hr = g_hj + (size_t)i * 64;
        float p = hr[lane] * sW[lane] + hr[lane + 32] * sW[lane + 32];
#pragma unroll
        for (int o = 16; o > 0; o >>= 1) p += __shfl_xor_sync(0xffffffffu, p, o);
        mx = fmaxf(mx, p);
    }
    if (lane == 0) rmax[warp] = mx;
    __syncthreads();
    float bmax = -1e30f;
#pragma unroll
    for (int wq = 0; wq < 8; wq++) bmax = fmaxf(bmax, rmax[wq]);

    float a0 = 0.f, a1 = 0.f, se = 0.f;
    for (int i = lo + warp; i < hi; i += 8) {
        const float* hr = g_hj + (size_t)i * 64;
        float h0 = hr[lane], h1 = hr[lane + 32];
        float p = h0 * sW[lane] + h1 * sW[lane + 32];
#pragma unroll
        for (int o = 16; o > 0; o >>= 1) p += __shfl_xor_sync(0xffffffffu, p, o);
        float ev = __expf(p - bmax);
        a0 += ev * h0; a1 += ev * h1; se += ev;
    }
    if (lane == 0) rsum[warp] = se;
    atomicAdd(&shg[lane], a0);
    atomicAdd(&shg[lane + 32], a1);
    __syncthreads();

    float setot = 0.f;
#pragma unroll
    for (int wq = 0; wq < 8; wq++) setot += rsum[wq];
    float inv = (setot > 0.f) ? 1.f / setot : 0.f;

    if (tid < 32) {
        float acc = b1[tid];
        for (int cc = 0; cc < 64; cc++) acc += shg[cc] * inv * W1[cc * 32 + tid];
        shid[tid] = acc > 0.f ? acc : 0.f;
    }
    __syncthreads();
    if (tid < 2) {
        float o = b2[tid];
#pragma unroll
        for (int j = 0; j < 32; j++) o += shid[j] * W2[j * 2 + tid];
        out[gidx * 2 + tid] = o;
    }
}

// ---------------- host ----------------
extern "C" void kernel_launch(void* const* d_in, const int* in_sizes, int n_in,
                              void* d_out, int out_size) {
    const float* x        = (const float*)d_in[0];
    const int*   ei       = (const int*)d_in[1];
    const int*   batch    = (const int*)d_in[2];
    const float* conv0_W  = (const float*)d_in[3];
    const float* c0_asrc  = (const float*)d_in[4];
    const float* c0_adst  = (const float*)d_in[5];
    const float* c0_bias  = (const float*)d_in[6];
    const float* pre0_W   = (const float*)d_in[7];
    const float* pre0_b   = (const float*)d_in[8];
    const float* convs_W  = (const float*)d_in[9];
    const float* cs_asrc  = (const float*)d_in[10];
    const float* cs_adst  = (const float*)d_in[11];
    const float* cs_bias  = (const float*)d_in[12];
    const float* bn_g     = (const float*)d_in[13];
    const float* bn_b     = (const float*)d_in[14];
    const float* bn_m     = (const float*)d_in[15];
    const float* bn_v     = (const float*)d_in[16];
    const float* jump_W   = (const float*)d_in[17];
    const float* jump_b   = (const float*)d_in[18];
    const float* att_W    = (const float*)d_in[19];
    const float* cls_W1   = (const float*)d_in[21];
    const float* cls_b1   = (const float*)d_in[22];
    const float* cls_W2   = (const float*)d_in[23];
    const float* cls_b2   = (const float*)d_in[24];

    int n = in_sizes[0] / 128;
    int e = in_sizes[1] / 2;

    unsigned *p_xh, *p_agg, *p_xhalf, *p_reph, *p_Bimg;
    float *p_rep, *p_hj;
    int *p_deg;
    cudaGetSymbolAddress((void**)&p_xh,    g_xh);
    cudaGetSymbolAddress((void**)&p_agg,   g_agg);
    cudaGetSymbolAddress((void**)&p_xhalf, g_xhalf);
    cudaGetSymbolAddress((void**)&p_reph,  g_reph);
    cudaGetSymbolAddress((void**)&p_Bimg,  g_Bimg);
    cudaGetSymbolAddress((void**)&p_rep,   g_rep);
    cudaGetSymbolAddress((void**)&p_hj,    g_hj);
    cudaGetSymbolAddress((void**)&p_deg,   g_deg);

    static cudaStream_t s2 = nullptr;
    static cudaEvent_t evFork = nullptr, evJoin = nullptr;
    if (!s2) {
        cudaStreamCreateWithFlags(&s2, cudaStreamNonBlocking);
        cudaEventCreateWithFlags(&evFork, cudaEventDisableTiming);
        cudaEventCreateWithFlags(&evJoin, cudaEventDisableTiming);
    }

    const int T = 256;
    int ebN  = (e + T - 1) / T;
    int wb   = (n + 7) / 8;
    int mg   = (n + 127) / 128;
    int nb2  = (n + 1023) / 1024;

    // ---- fork: CSR build on s2 concurrent with conversion + conv0 GEMM ----
    cudaEventRecord(evFork, 0);
    cudaStreamWaitEvent(s2, evFork, 0);

    cudaMemsetAsync(p_deg, 0, (size_t)n * sizeof(int), s2);
    count_kernel<<<ebN, T, 0, s2>>>(ei, e);
    scanA_kernel<<<nb2, 1024, 0, s2>>>(n);
    scanB_kernel<<<1, 1024, 0, s2>>>(nb2, n);
    scanC_kernel<<<nb2, 1024, 0, s2>>>(n);
    fill_edges_kernel<<<ebN, T, 0, s2>>>(ei, e);
    cudaEventRecord(evJoin, s2);

    // main stream: input conversions + layer-0 GEMM
    cvt_half_kernel<<<(n * 64 + T - 1) / T, T>>>(x, p_xhalf, n * 64);
    prep_B_kernel<<<46, 256>>>(conv0_W, pre0_W, convs_W, jump_W);
    gemm_tc<0,0,1,1,0><<<dim3(4, mg), 256>>>(p_xhalf, p_Bimg, nullptr, nullptr, nullptr,
                                             nullptr, nullptr, c0_asrc, c0_adst,
                                             p_xh, n, 128, 256);

    cudaStreamWaitEvent(0, evJoin, 0);

    // ---- layer 0 aggregation + pre0 (bias+BN+ELU fused, fp32 + half dual) ----
    agg_concat_kernel<<<wb, T>>>(c0_bias, n);
    gemm_tc<0,2,0,0,1><<<dim3(1, mg), 256>>>(p_agg, p_Bimg + 24576, pre0_b, bn_g, bn_b,
                                             bn_m, bn_v, nullptr, nullptr,
                                             p_rep, n, 256, 64);

    // ---- layers 1,2 ----
    for (int i = 0; i < 2; i++) {
        const float* rin  = p_rep + (size_t)i * NMAX * 64;
        float*       rout = p_rep + (size_t)(i + 1) * NMAX * 64;
        gemm_tc<0,0,1,1,0><<<dim3(4, mg), 256>>>(p_reph + (size_t)i * NMAX * 32,
                                                 p_Bimg + 36864 + i * 12288,
                                                 nullptr, nullptr, nullptr, nullptr, nullptr,
                                                 cs_asrc + i * 256, cs_adst + i * 256,
                                                 p_xh, n, 64, 256);
        agg_mean_kernel<<<wb, T>>>(cs_bias + i * 64,
                                   bn_g + (i + 1) * 64, bn_b + (i + 1) * 64,
                                   bn_m + (i + 1) * 64, bn_v + (i + 1) * 64,
                                   rin, rout, p_reph + (size_t)(i + 1) * NMAX * 32, n);
    }

    // ---- jumping knowledge GEMM reads g_reph layers (AMODE=1), fused bias ----
    gemm_tc<1,1,0,0,0><<<dim3(1, mg), 256>>>(p_reph, p_Bimg + 61440, jump_b, nullptr, nullptr,
                                             nullptr, nullptr, nullptr, nullptr,
                                             p_hj, n, 192, 64);

    // ---- fused pooling + classifier ----
    pool_cls_kernel<<<GRAPHS, 256>>>(att_W, batch, cls_W1, cls_b1, cls_W2, cls_b2,
                                     (float*)d_out, n);
}